// round 11
// baseline (speedup 1.0000x reference)
#include <cuda_runtime.h>
#include <cuda_fp16.h>
#include <cstdint>

#define NC 384
#define NH 6
#define HD 64
#define NB 64
#define NT 256
#define NM (NB*NT)
#define SOFT_SCALE 0.125f

// fp16 scratch (allocation-free rule: __device__ globals)
__device__ __align__(128) __half g_x16[(size_t)NM*NC];
__device__ __align__(128) __half g_wqkv16[(size_t)NH*3*HD*NC];  // [h][mat][n=64][k=384]
__device__ __align__(128) __half g_wp16[(size_t)NC*NC];         // [n=384][k=384]
__device__ __align__(128) __half g_q16[(size_t)NB*NH*NT*HD];    // pre-scaled by 1/8
__device__ __align__(128) __half g_k16[(size_t)NB*NH*NT*HD];
__device__ __align__(128) __half g_v16[(size_t)NB*NH*NT*HD];
__device__ __align__(128) __half g_att16[(size_t)NB*NH*NT*HD];

#define SWZ128(b) ((b) ^ (((b) >> 3) & 0x70))

static __device__ __forceinline__ uint32_t smem_u32(const void* p) {
    uint32_t a;
    asm("{ .reg .u64 t; cvta.to.shared.u64 t, %1; cvt.u32.u64 %0, t; }"
        : "=r"(a) : "l"(p));
    return a;
}
static __device__ __forceinline__ void ldsm_x4(
    uint32_t& r0, uint32_t& r1, uint32_t& r2, uint32_t& r3, uint32_t addr)
{
    asm volatile("ldmatrix.sync.aligned.m8n8.x4.shared.b16 {%0,%1,%2,%3}, [%4];"
                 : "=r"(r0), "=r"(r1), "=r"(r2), "=r"(r3) : "r"(addr));
}
static __device__ __forceinline__ void ldsm_x4_t(
    uint32_t& r0, uint32_t& r1, uint32_t& r2, uint32_t& r3, uint32_t addr)
{
    asm volatile("ldmatrix.sync.aligned.m8n8.x4.trans.shared.b16 {%0,%1,%2,%3}, [%4];"
                 : "=r"(r0), "=r"(r1), "=r"(r2), "=r"(r3) : "r"(addr));
}
static __device__ __forceinline__ void mma16816(
    float* c, uint32_t a0, uint32_t a1, uint32_t a2, uint32_t a3,
    uint32_t b0, uint32_t b1)
{
    asm volatile(
        "mma.sync.aligned.m16n8k16.row.col.f32.f16.f16.f32 "
        "{%0,%1,%2,%3}, {%4,%5,%6,%7}, {%8,%9}, {%0,%1,%2,%3};"
        : "+f"(c[0]), "+f"(c[1]), "+f"(c[2]), "+f"(c[3])
        : "r"(a0), "r"(a1), "r"(a2), "r"(a3), "r"(b0), "r"(b1));
}
static __device__ __forceinline__ uint32_t f2h2(float a, float b) {
    __half2 h = __floats2half2_rn(a, b);
    return *reinterpret_cast<uint32_t*>(&h);
}
#define CP_ASYNC16(d, s) \
    asm volatile("cp.async.ca.shared.global [%0], [%1], 16;" :: "r"(d), "l"(s))
#define CP_COMMIT() asm volatile("cp.async.commit_group;" ::: "memory")
#define CP_WAIT0()  asm volatile("cp.async.wait_group 0;" ::: "memory")
#define CP_WAIT1()  asm volatile("cp.async.wait_group 1;" ::: "memory")

// ===========================================================================
// Prologue: converts. blocks [0,3072): x -> fp16. blocks [3072,3096): weights.
// ===========================================================================
__global__ __launch_bounds__(256) void convert_all_kernel(
    const float* __restrict__ x,
    const float* __restrict__ Wq, const float* __restrict__ Wk,
    const float* __restrict__ Wv, const float* __restrict__ Wp)
{
    __shared__ __half tw[64 * 384];
    int tid = threadIdx.x;

    if (blockIdx.x < 3072) {
        size_t i = ((size_t)blockIdx.x * 256 + tid) * 8;
        float4 u = *(const float4*)(x + i);
        float4 v = *(const float4*)(x + i + 4);
        *(uint4*)(g_x16 + i) = make_uint4(f2h2(u.x,u.y), f2h2(u.z,u.w),
                                          f2h2(v.x,v.y), f2h2(v.z,v.w));
        return;
    }
    int blk = blockIdx.x - 3072;
    if (blk < 18) {
        const float* Wsrcs[3] = {Wq, Wk, Wv};
        int mat = blk / 6, h = blk % 6;
        const float* W = Wsrcs[mat] + (size_t)h * NC * HD;
        for (int e = tid; e < 384 * 16; e += 256) {
            int k = e >> 4, n4 = e & 15;
            float4 w = *(const float4*)(W + (size_t)k * HD + n4 * 4);
            tw[(n4*4+0) * 384 + k] = __float2half_rn(w.x);
            tw[(n4*4+1) * 384 + k] = __float2half_rn(w.y);
            tw[(n4*4+2) * 384 + k] = __float2half_rn(w.z);
            tw[(n4*4+3) * 384 + k] = __float2half_rn(w.w);
        }
        __syncthreads();
        uint4* dst = (uint4*)(g_wqkv16 + (size_t)(h * 3 + mat) * 64 * 384);
        for (int e = tid; e < 64 * 48; e += 256)
            dst[e] = *(uint4*)(tw + e * 8);
    } else {
        int n0 = (blk - 18) * 64;
        for (int e = tid; e < 384 * 16; e += 256) {
            int k = e >> 4, n4 = e & 15;
            float4 w = *(const float4*)(Wp + (size_t)k * NC + n0 + n4 * 4);
            tw[(n4*4+0) * 384 + k] = __float2half_rn(w.x);
            tw[(n4*4+1) * 384 + k] = __float2half_rn(w.y);
            tw[(n4*4+2) * 384 + k] = __float2half_rn(w.z);
            tw[(n4*4+3) * 384 + k] = __float2half_rn(w.w);
        }
        __syncthreads();
        uint4* dst = (uint4*)(g_wp16 + (size_t)n0 * 384);
        for (int e = tid; e < 64 * 48; e += 256)
            dst[e] = *(uint4*)(tw + e * 8);
    }
}

// ===========================================================================
// Kernel 1: QKV GEMM, 3 mats fused per head (n=192). grid (128, 6),
// block 384 (12 warps): rt=wid&3 (m 32-row tile), ct=wid>>2 (mat 0..2).
// Half-row double buffer: 128B smem rows hold 2 k-chunks of 32 (even chunk in
// bytes 0..63, odd in 64..127). 12 chunks, cp.async pipeline depth 1.
// Q outputs pre-scaled by SOFT_SCALE.
// ===========================================================================
__global__ __launch_bounds__(384) void qkv_tc_kernel()
{
    __shared__ __align__(1024) __half smA[128*64];   // 16KB = 2 chunk-halves
    __shared__ __align__(1024) __half smB[192*64];   // 24KB

    int tid = threadIdx.x;
    int wid = tid >> 5, lane = tid & 31;
    int rt = wid & 3, ct = wid >> 2;     // ct == mat
    int h  = blockIdx.y;
    int m0 = blockIdx.x * 128;

    const uint32_t sAu = smem_u32(smA);
    const uint32_t sBu = smem_u32(smB);
    const __half* wsrc = g_wqkv16 + (size_t)h * 192 * 384;

    float acc[2][8][4] = {};

    auto issue = [&](int c) {
        int k0 = c * 32, hb = (c & 1) * 64;  // byte offset within row
        #pragma unroll
        for (int i = 0; i < 2; i++) {        // A: 512 items
            int e = tid + i * 384;
            if (e < 512) {
                int r = e >> 2, g = e & 3;
                CP_ASYNC16(sAu + SWZ128(r * 128 + hb + g * 16),
                           g_x16 + (size_t)(m0 + r) * NC + k0 + g * 8);
            }
        }
        #pragma unroll
        for (int i = 0; i < 2; i++) {        // B: 768 items
            int e = tid + i * 384;
            int n = e >> 2, g = e & 3;
            CP_ASYNC16(sBu + SWZ128(n * 128 + hb + g * 16),
                       wsrc + (size_t)n * 384 + k0 + g * 8);
        }
    };

    issue(0); CP_COMMIT();
    for (int c = 0; c < 12; c++) {
        if (c < 11) { issue(c + 1); CP_COMMIT(); CP_WAIT1(); }
        else        { CP_WAIT0(); }
        __syncthreads();
        int hb16 = (c & 1) * 4;              // col16 offset of this chunk
        #pragma unroll
        for (int ks = 0; ks < 2; ks++) {
            int col16 = hb16 + ks * 2 + (lane >> 4);
            uint32_t a[2][4];
            #pragma unroll
            for (int mb = 0; mb < 2; mb++) {
                int row = rt * 32 + mb * 16 + (lane & 15);
                ldsm_x4(a[mb][0], a[mb][1], a[mb][2], a[mb][3],
                        sAu + SWZ128(row * 128 + col16 * 16));
            }
            uint32_t b[8][2];
            #pragma unroll
            for (int np = 0; np < 4; np++) {
                int n = ct * 64 + np * 16 + (lane & 15);
                ldsm_x4(b[np*2][0], b[np*2+1][0], b[np*2][1], b[np*2+1][1],
                        sBu + SWZ128(n * 128 + col16 * 16));
            }
            #pragma unroll
            for (int mb = 0; mb < 2; mb++)
                #pragma unroll
                for (int nb = 0; nb < 8; nb++)
                    mma16816(acc[mb][nb], a[mb][0], a[mb][1], a[mb][2], a[mb][3],
                             b[nb][0], b[nb][1]);
        }
        __syncthreads();   // all reads of this half done before c+2 overwrites it
    }

    __half* const outs3[3] = {g_q16, g_k16, g_v16};
    __half* outp = outs3[ct];
    float sc = (ct == 0) ? SOFT_SCALE : 1.0f;
    #pragma unroll
    for (int mb = 0; mb < 2; mb++) {
        int mg = m0 + rt * 32 + mb * 16 + (lane >> 2);
        int b = mg >> 8, t = mg & 255;
        __half* orow = outp + ((size_t)(b * NH + h) * NT + t) * HD;
        #pragma unroll
        for (int nb = 0; nb < 8; nb++) {
            int n = nb * 8 + (lane & 3) * 2;
            *(uint32_t*)(orow + n)        = f2h2(acc[mb][nb][0]*sc, acc[mb][nb][1]*sc);
            *(uint32_t*)(orow + 8*HD + n) = f2h2(acc[mb][nb][2]*sc, acc[mb][nb][3]*sc);
        }
    }
}

// ===========================================================================
// Kernel 2: causal flash attention. grid (2, NB*NH), block 256 (8 warps).
// CTA = 128 q-rows, warp = 16 q-rows, Q frags in registers. (unchanged)
// ===========================================================================
__global__ __launch_bounds__(256) void attn_tc_kernel()
{
    __shared__ __align__(1024) __half smK[2][64*64];
    __shared__ __align__(1024) __half smV[2][64*64];

    int tid = threadIdx.x;
    int wid = tid >> 5, lane = tid & 31;
    int qt2 = blockIdx.x;
    int bh = blockIdx.y;

    const uint32_t sKu[2] = {smem_u32(smK[0]), smem_u32(smK[1])};
    const uint32_t sVu[2] = {smem_u32(smV[0]), smem_u32(smV[1])};
    const __half* qbase = g_q16 + (size_t)bh * NT * HD;
    const __half* kbase = g_k16 + (size_t)bh * NT * HD;
    const __half* vbase = g_v16 + (size_t)bh * NT * HD;

    #pragma unroll
    for (int i = 0; i < 4; i++) {
        int e = tid + i * 256;
        int r = e >> 3, g = e & 7;
        uint32_t dst = (r < 64) ? sKu[0] + SWZ128(r * 128 + g * 16)
                                : sKu[1] + SWZ128((r - 64) * 128 + g * 16);
        CP_ASYNC16(dst, qbase + (size_t)(qt2*128 + r) * HD + g * 8);
    }
    CP_COMMIT(); CP_WAIT0();
    __syncthreads();

    uint32_t qf[4][4];
    {
        int qrow = wid * 16 + (lane & 15);
        uint32_t qsrc = (qrow < 64) ? sKu[0] : sKu[1];
        int qr = qrow & 63;
        #pragma unroll
        for (int ks = 0; ks < 4; ks++) {
            int col16 = ks * 2 + (lane >> 4);
            ldsm_x4(qf[ks][0], qf[ks][1], qf[ks][2], qf[ks][3],
                    qsrc + SWZ128(qr * 128 + col16 * 16));
        }
    }
    __syncthreads();

    auto issueKV = [&](int st) {
        int bf = st & 1;
        #pragma unroll
        for (int i = 0; i < 2; i++) {
            int e = tid + i * 256;
            int r = e >> 3, g = e & 7;
            CP_ASYNC16(sKu[bf] + SWZ128(r * 128 + g * 16),
                       kbase + (size_t)(st*64 + r) * HD + g * 8);
            CP_ASYNC16(sVu[bf] + SWZ128(r * 128 + g * 16),
                       vbase + (size_t)(st*64 + r) * HD + g * 8);
        }
    };
    issueKV(0); CP_COMMIT();

    float o[8][4] = {};
    float mrow[2] = {-1e30f, -1e30f};
    float lrow[2] = {};
    int lastTile = qt2 * 2 + (wid >> 2);
    int ntiles = qt2 * 2 + 2;

    for (int st = 0; st < ntiles; st++) {
        if (st < ntiles - 1) { issueKV(st + 1); CP_COMMIT(); CP_WAIT1(); }
        else                 { CP_WAIT0(); }
        __syncthreads();
        int bf = st & 1;

        if (st <= lastTile) {
            float sacc[8][4] = {};
            #pragma unroll
            for (int ks = 0; ks < 4; ks++) {
                uint32_t b[8][2];
                int col16 = ks * 2 + (lane >> 4);
                #pragma unroll
                for (int np = 0; np < 4; np++) {
                    int n = np * 16 + (lane & 15);
                    ldsm_x4(b[np*2][0], b[np*2+1][0], b[np*2][1], b[np*2+1][1],
                            sKu[bf] + SWZ128(n * 128 + col16 * 16));
                }
                #pragma unroll
                for (int nb = 0; nb < 8; nb++)
                    mma16816(sacc[nb], qf[ks][0], qf[ks][1], qf[ks][2], qf[ks][3],
                             b[nb][0], b[nb][1]);
            }

            if (st == lastTile) {
                int r0 = qt2*128 + wid*16 + (lane >> 2);
                #pragma unroll
                for (int nb = 0; nb < 8; nb++) {
                    int cg = st*64 + nb*8 + (lane & 3) * 2;
                    if (cg     > r0    ) sacc[nb][0] = -1e30f;
                    if (cg + 1 > r0    ) sacc[nb][1] = -1e30f;
                    if (cg     > r0 + 8) sacc[nb][2] = -1e30f;
                    if (cg + 1 > r0 + 8) sacc[nb][3] = -1e30f;
                }
            }

            #pragma unroll
            for (int hf = 0; hf < 2; hf++) {
                float mx = -1e30f;
                #pragma unroll
                for (int nb = 0; nb < 8; nb++)
                    mx = fmaxf(mx, fmaxf(sacc[nb][hf*2], sacc[nb][hf*2+1]));
                mx = fmaxf(mx, __shfl_xor_sync(0xffffffffu, mx, 1));
                mx = fmaxf(mx, __shfl_xor_sync(0xffffffffu, mx, 2));
                float mnew = fmaxf(mrow[hf], mx);
                float corr = __expf(mrow[hf] - mnew);
                float rs = 0.f;
                #pragma unroll
                for (int nb = 0; nb < 8; nb++) {
                    float p0 = __expf(sacc[nb][hf*2]   - mnew);
                    float p1 = __expf(sacc[nb][hf*2+1] - mnew);
                    sacc[nb][hf*2] = p0; sacc[nb][hf*2+1] = p1;
                    rs += p0 + p1;
                }
                rs += __shfl_xor_sync(0xffffffffu, rs, 1);
                rs += __shfl_xor_sync(0xffffffffu, rs, 2);
                lrow[hf] = lrow[hf] * corr + rs;
                mrow[hf] = mnew;
                #pragma unroll
                for (int nb = 0; nb < 8; nb++) {
                    o[nb][hf*2]   *= corr;
                    o[nb][hf*2+1] *= corr;
                }
            }

            #pragma unroll
            for (int ks = 0; ks < 4; ks++) {
                uint32_t pa0 = f2h2(sacc[ks*2  ][0], sacc[ks*2  ][1]);
                uint32_t pa1 = f2h2(sacc[ks*2  ][2], sacc[ks*2  ][3]);
                uint32_t pa2 = f2h2(sacc[ks*2+1][0], sacc[ks*2+1][1]);
                uint32_t pa3 = f2h2(sacc[ks*2+1][2], sacc[ks*2+1][3]);
                #pragma unroll
                for (int np = 0; np < 4; np++) {
                    int m = lane >> 3;
                    int row = ks * 16 + ((m & 1) << 3) + (lane & 7);
                    int colb = (np * 16 + ((m & 2) << 2)) * 2;
                    uint32_t v0, v1, v2, v3;
                    ldsm_x4_t(v0, v1, v2, v3, sVu[bf] + SWZ128(row * 128 + colb));
                    mma16816(o[np*2],   pa0, pa1, pa2, pa3, v0, v1);
                    mma16816(o[np*2+1], pa0, pa1, pa2, pa3, v2, v3);
                }
            }
        }
        __syncthreads();
    }

    float inv0 = 1.0f / lrow[0], inv1 = 1.0f / lrow[1];
    int t0 = qt2*128 + wid*16 + (lane >> 2);
    __half* ob = g_att16 + ((size_t)bh * NT + t0) * HD;
    #pragma unroll
    for (int nb = 0; nb < 8; nb++) {
        int n = nb*8 + (lane & 3) * 2;
        *(uint32_t*)(ob + n)        = f2h2(o[nb][0]*inv0, o[nb][1]*inv0);
        *(uint32_t*)(ob + 8*HD + n) = f2h2(o[nb][2]*inv1, o[nb][3]*inv1);
    }
}

// ===========================================================================
// Kernel 3: output projection + bias. grid (128, 2), block 384 (12 warps).
// CTA: m=128, n=192 (ct=wid>>2 picks 64-wide n block), K=12 chunks of 32,
// half-row double buffer identical to qkv. A's head = chunk>>1.
// ===========================================================================
__global__ __launch_bounds__(384) void proj_tc_kernel(
    const float* __restrict__ bp, float* __restrict__ out)
{
    __shared__ __align__(1024) __half smA[128*64];
    __shared__ __align__(1024) __half smB[192*64];

    int tid = threadIdx.x;
    int wid = tid >> 5, lane = tid & 31;
    int rt = wid & 3, ct = wid >> 2;
    int m0 = blockIdx.x * 128;
    int e0 = blockIdx.y * 192;
    int b  = m0 >> 8;
    int t0 = m0 & 255;

    const uint32_t sAu = smem_u32(smA);
    const uint32_t sBu = smem_u32(smB);

    float acc[2][8][4] = {};

    auto issue = [&](int c) {
        int hc = c >> 1, ko = (c & 1) * 32, hb = (c & 1) * 64;
        const __half* abase = g_att16 + ((size_t)(b * NH + hc) * NT + t0) * HD + ko;
        #pragma unroll
        for (int i = 0; i < 2; i++) {
            int e = tid + i * 384;
            if (e < 512) {
                int r = e >> 2, g = e & 3;
                CP_ASYNC16(sAu + SWZ128(r * 128 + hb + g * 16),
                           abase + (size_t)r * HD + g * 8);
            }
        }
        #pragma unroll
        for (int i = 0; i < 2; i++) {
            int e = tid + i * 384;
            int n = e >> 2, g = e & 3;
            CP_ASYNC16(sBu + SWZ128(n * 128 + hb + g * 16),
                       g_wp16 + (size_t)(e0 + n) * 384 + c * 32 + g * 8);
        }
    };

    issue(0); CP_COMMIT();
    for (int c = 0; c < 12; c++) {
        if (c < 11) { issue(c + 1); CP_COMMIT(); CP_WAIT1(); }
        else        { CP_WAIT0(); }
        __syncthreads();
        int hb16 = (c & 1) * 4;
        #pragma unroll
        for (int ks = 0; ks < 2; ks++) {
            int col16 = hb16 + ks * 2 + (lane >> 4);
            uint32_t a[2][4];
            #pragma unroll
            for (int mb = 0; mb < 2; mb++) {
                int row = rt * 32 + mb * 16 + (lane & 15);
                ldsm_x4(a[mb][0], a[mb][1], a[mb][2], a[mb][3],
                        sAu + SWZ128(row * 128 + col16 * 16));
            }
            uint32_t bb[8][2];
            #pragma unroll
            for (int np = 0; np < 4; np++) {
                int n = ct * 64 + np * 16 + (lane & 15);
                ldsm_x4(bb[np*2][0], bb[np*2+1][0], bb[np*2][1], bb[np*2+1][1],
                        sBu + SWZ128(n * 128 + col16 * 16));
            }
            #pragma unroll
            for (int mb = 0; mb < 2; mb++)
                #pragma unroll
                for (int nb = 0; nb < 8; nb++)
                    mma16816(acc[mb][nb], a[mb][0], a[mb][1], a[mb][2], a[mb][3],
                             bb[nb][0], bb[nb][1]);
        }
        __syncthreads();
    }

    #pragma unroll
    for (int mb = 0; mb < 2; mb++) {
        int mg = m0 + rt * 32 + mb * 16 + (lane >> 2);
        float* orow = out + (size_t)mg * NC + e0;
        #pragma unroll
        for (int nb = 0; nb < 8; nb++) {
            int n = ct * 64 + nb * 8 + (lane & 3) * 2;
            float2 bb2 = *(const float2*)(bp + e0 + n);
            *(float2*)(orow + n) =
                make_float2(acc[mb][nb][0] + bb2.x, acc[mb][nb][1] + bb2.y);
            *(float2*)(orow + 8*NC + n) =
                make_float2(acc[mb][nb][2] + bb2.x, acc[mb][nb][3] + bb2.y);
        }
    }
}

// ---------------------------------------------------------------------------

extern "C" void kernel_launch(void* const* d_in, const int* in_sizes, int n_in,
                              void* d_out, int out_size)
{
    const float* x  = (const float*)d_in[0];
    const float* Wq = (const float*)d_in[1];
    const float* Wk = (const float*)d_in[2];
    const float* Wv = (const float*)d_in[3];
    const float* Wp = (const float*)d_in[4];
    const float* bp = (const float*)d_in[5];
    float* out = (float*)d_out;

    convert_all_kernel<<<3096, 256>>>(x, Wq, Wk, Wv, Wp);
    qkv_tc_kernel<<<dim3(NM/128, NH), 384>>>();
    attn_tc_kernel<<<dim3(2, NB*NH), 256>>>();
    proj_tc_kernel<<<dim3(NM/128, NC/192), 384>>>(bp, out);
}

// round 12
// speedup vs baseline: 1.0637x; 1.0637x over previous
#include <cuda_runtime.h>
#include <cuda_fp16.h>
#include <cstdint>

#define NC 384
#define NH 6
#define HD 64
#define NB 64
#define NT 256
#define NM (NB*NT)
#define SOFT_SCALE 0.125f

// fp16 scratch (allocation-free rule: __device__ globals)
__device__ __align__(128) __half g_x16[(size_t)NM*NC];
__device__ __align__(128) __half g_wqkv16[(size_t)NH*3*HD*NC];  // [h][mat][n=64][k=384]
__device__ __align__(128) __half g_wp16[(size_t)NC*NC];         // [n=384][k=384]
__device__ __align__(128) __half g_q16[(size_t)NB*NH*NT*HD];    // pre-scaled by 1/8
__device__ __align__(128) __half g_k16[(size_t)NB*NH*NT*HD];
__device__ __align__(128) __half g_v16[(size_t)NB*NH*NT*HD];
__device__ __align__(128) __half g_att16[(size_t)NB*NH*NT*HD];

#define SWZ128(b) ((b) ^ (((b) >> 3) & 0x70))

static __device__ __forceinline__ uint32_t smem_u32(const void* p) {
    uint32_t a;
    asm("{ .reg .u64 t; cvta.to.shared.u64 t, %1; cvt.u32.u64 %0, t; }"
        : "=r"(a) : "l"(p));
    return a;
}
static __device__ __forceinline__ void ldsm_x4(
    uint32_t& r0, uint32_t& r1, uint32_t& r2, uint32_t& r3, uint32_t addr)
{
    asm volatile("ldmatrix.sync.aligned.m8n8.x4.shared.b16 {%0,%1,%2,%3}, [%4];"
                 : "=r"(r0), "=r"(r1), "=r"(r2), "=r"(r3) : "r"(addr));
}
static __device__ __forceinline__ void ldsm_x4_t(
    uint32_t& r0, uint32_t& r1, uint32_t& r2, uint32_t& r3, uint32_t addr)
{
    asm volatile("ldmatrix.sync.aligned.m8n8.x4.trans.shared.b16 {%0,%1,%2,%3}, [%4];"
                 : "=r"(r0), "=r"(r1), "=r"(r2), "=r"(r3) : "r"(addr));
}
static __device__ __forceinline__ void mma16816(
    float* c, uint32_t a0, uint32_t a1, uint32_t a2, uint32_t a3,
    uint32_t b0, uint32_t b1)
{
    asm volatile(
        "mma.sync.aligned.m16n8k16.row.col.f32.f16.f16.f32 "
        "{%0,%1,%2,%3}, {%4,%5,%6,%7}, {%8,%9}, {%0,%1,%2,%3};"
        : "+f"(c[0]), "+f"(c[1]), "+f"(c[2]), "+f"(c[3])
        : "r"(a0), "r"(a1), "r"(a2), "r"(a3), "r"(b0), "r"(b1));
}
static __device__ __forceinline__ uint32_t f2h2(float a, float b) {
    __half2 h = __floats2half2_rn(a, b);
    return *reinterpret_cast<uint32_t*>(&h);
}
#define CP_ASYNC16(d, s) \
    asm volatile("cp.async.ca.shared.global [%0], [%1], 16;" :: "r"(d), "l"(s))
#define CP_COMMIT() asm volatile("cp.async.commit_group;" ::: "memory")
#define CP_WAIT0()  asm volatile("cp.async.wait_group 0;" ::: "memory")
#define CP_WAIT1()  asm volatile("cp.async.wait_group 1;" ::: "memory")

// ===========================================================================
// Prologue: converts. blocks [0,3072): x -> fp16. blocks [3072,3096): weights.
// ===========================================================================
__global__ __launch_bounds__(256) void convert_all_kernel(
    const float* __restrict__ x,
    const float* __restrict__ Wq, const float* __restrict__ Wk,
    const float* __restrict__ Wv, const float* __restrict__ Wp)
{
    __shared__ __half tw[64 * 384];
    int tid = threadIdx.x;

    if (blockIdx.x < 3072) {
        size_t i = ((size_t)blockIdx.x * 256 + tid) * 8;
        float4 u = *(const float4*)(x + i);
        float4 v = *(const float4*)(x + i + 4);
        *(uint4*)(g_x16 + i) = make_uint4(f2h2(u.x,u.y), f2h2(u.z,u.w),
                                          f2h2(v.x,v.y), f2h2(v.z,v.w));
        return;
    }
    int blk = blockIdx.x - 3072;
    if (blk < 18) {
        const float* Wsrcs[3] = {Wq, Wk, Wv};
        int mat = blk / 6, h = blk % 6;
        const float* W = Wsrcs[mat] + (size_t)h * NC * HD;
        for (int e = tid; e < 384 * 16; e += 256) {
            int k = e >> 4, n4 = e & 15;
            float4 w = *(const float4*)(W + (size_t)k * HD + n4 * 4);
            tw[(n4*4+0) * 384 + k] = __float2half_rn(w.x);
            tw[(n4*4+1) * 384 + k] = __float2half_rn(w.y);
            tw[(n4*4+2) * 384 + k] = __float2half_rn(w.z);
            tw[(n4*4+3) * 384 + k] = __float2half_rn(w.w);
        }
        __syncthreads();
        uint4* dst = (uint4*)(g_wqkv16 + (size_t)(h * 3 + mat) * 64 * 384);
        for (int e = tid; e < 64 * 48; e += 256)
            dst[e] = *(uint4*)(tw + e * 8);
    } else {
        int n0 = (blk - 18) * 64;
        for (int e = tid; e < 384 * 16; e += 256) {
            int k = e >> 4, n4 = e & 15;
            float4 w = *(const float4*)(Wp + (size_t)k * NC + n0 + n4 * 4);
            tw[(n4*4+0) * 384 + k] = __float2half_rn(w.x);
            tw[(n4*4+1) * 384 + k] = __float2half_rn(w.y);
            tw[(n4*4+2) * 384 + k] = __float2half_rn(w.z);
            tw[(n4*4+3) * 384 + k] = __float2half_rn(w.w);
        }
        __syncthreads();
        uint4* dst = (uint4*)(g_wp16 + (size_t)n0 * 384);
        for (int e = tid; e < 64 * 48; e += 256)
            dst[e] = *(uint4*)(tw + e * 8);
    }
}

// ===========================================================================
// Kernel 1: QKV GEMM, 3 mats fused per head (n=192). grid (128, 6),
// block 384 (12 warps): rt=wid&3 (m 32-row tile), ct=wid>>2 (mat 0..2).
// Single-buffered smem (A 16KB + B 24KB = 40KB), K = 6 chunks of 64.
// Q outputs pre-scaled by SOFT_SCALE.  (R9 version, unchanged)
// ===========================================================================
__global__ __launch_bounds__(384) void qkv_tc_kernel()
{
    __shared__ __align__(1024) __half smA[128*64];
    __shared__ __align__(1024) __half smB[192*64];

    int tid = threadIdx.x;
    int wid = tid >> 5, lane = tid & 31;
    int rt = wid & 3, ct = wid >> 2;     // ct == mat
    int h  = blockIdx.y;
    int m0 = blockIdx.x * 128;

    const uint32_t sAu = smem_u32(smA);
    const uint32_t sBu = smem_u32(smB);
    const __half* wsrc = g_wqkv16 + (size_t)h * 192 * 384;

    float acc[2][8][4] = {};

    for (int c = 0; c < 6; c++) {
        int c0 = c * 64;
        for (int e = tid; e < 1024; e += 384) {
            int r = e >> 3, g = e & 7;
            CP_ASYNC16(sAu + SWZ128(r * 128 + g * 16),
                       g_x16 + (size_t)(m0 + r) * NC + c0 + g * 8);
        }
        for (int e = tid; e < 1536; e += 384) {
            int n = e >> 3, g = e & 7;
            CP_ASYNC16(sBu + SWZ128(n * 128 + g * 16),
                       wsrc + (size_t)n * 384 + c0 + g * 8);
        }
        CP_COMMIT(); CP_WAIT0();
        __syncthreads();

        #pragma unroll
        for (int ks = 0; ks < 4; ks++) {
            int col16 = ks * 2 + (lane >> 4);
            uint32_t a[2][4];
            #pragma unroll
            for (int mb = 0; mb < 2; mb++) {
                int row = rt * 32 + mb * 16 + (lane & 15);
                ldsm_x4(a[mb][0], a[mb][1], a[mb][2], a[mb][3],
                        sAu + SWZ128(row * 128 + col16 * 16));
            }
            uint32_t b[8][2];
            #pragma unroll
            for (int np = 0; np < 4; np++) {
                int n = ct * 64 + np * 16 + (lane & 15);
                ldsm_x4(b[np*2][0], b[np*2+1][0], b[np*2][1], b[np*2+1][1],
                        sBu + SWZ128(n * 128 + col16 * 16));
            }
            #pragma unroll
            for (int mb = 0; mb < 2; mb++)
                #pragma unroll
                for (int nb = 0; nb < 8; nb++)
                    mma16816(acc[mb][nb], a[mb][0], a[mb][1], a[mb][2], a[mb][3],
                             b[nb][0], b[nb][1]);
        }
        __syncthreads();
    }

    __half* const outs3[3] = {g_q16, g_k16, g_v16};
    __half* outp = outs3[ct];
    float sc = (ct == 0) ? SOFT_SCALE : 1.0f;
    #pragma unroll
    for (int mb = 0; mb < 2; mb++) {
        int mg = m0 + rt * 32 + mb * 16 + (lane >> 2);
        int b = mg >> 8, t = mg & 255;
        __half* orow = outp + ((size_t)(b * NH + h) * NT + t) * HD;
        #pragma unroll
        for (int nb = 0; nb < 8; nb++) {
            int n = nb * 8 + (lane & 3) * 2;
            *(uint32_t*)(orow + n)        = f2h2(acc[mb][nb][0]*sc, acc[mb][nb][1]*sc);
            *(uint32_t*)(orow + 8*HD + n) = f2h2(acc[mb][nb][2]*sc, acc[mb][nb][3]*sc);
        }
    }
}

// ===========================================================================
// Kernel 2: causal flash attention. grid (2, NB*NH), block 256 (8 warps).
// CTA = 128 q-rows, warp = 16 q-rows, Q frags in registers. (R9, unchanged)
// ===========================================================================
__global__ __launch_bounds__(256) void attn_tc_kernel()
{
    __shared__ __align__(1024) __half smK[2][64*64];
    __shared__ __align__(1024) __half smV[2][64*64];

    int tid = threadIdx.x;
    int wid = tid >> 5, lane = tid & 31;
    int qt2 = blockIdx.x;
    int bh = blockIdx.y;

    const uint32_t sKu[2] = {smem_u32(smK[0]), smem_u32(smK[1])};
    const uint32_t sVu[2] = {smem_u32(smV[0]), smem_u32(smV[1])};
    const __half* qbase = g_q16 + (size_t)bh * NT * HD;
    const __half* kbase = g_k16 + (size_t)bh * NT * HD;
    const __half* vbase = g_v16 + (size_t)bh * NT * HD;

    #pragma unroll
    for (int i = 0; i < 4; i++) {
        int e = tid + i * 256;
        int r = e >> 3, g = e & 7;
        uint32_t dst = (r < 64) ? sKu[0] + SWZ128(r * 128 + g * 16)
                                : sKu[1] + SWZ128((r - 64) * 128 + g * 16);
        CP_ASYNC16(dst, qbase + (size_t)(qt2*128 + r) * HD + g * 8);
    }
    CP_COMMIT(); CP_WAIT0();
    __syncthreads();

    uint32_t qf[4][4];
    {
        int qrow = wid * 16 + (lane & 15);
        uint32_t qsrc = (qrow < 64) ? sKu[0] : sKu[1];
        int qr = qrow & 63;
        #pragma unroll
        for (int ks = 0; ks < 4; ks++) {
            int col16 = ks * 2 + (lane >> 4);
            ldsm_x4(qf[ks][0], qf[ks][1], qf[ks][2], qf[ks][3],
                    qsrc + SWZ128(qr * 128 + col16 * 16));
        }
    }
    __syncthreads();

    auto issueKV = [&](int st) {
        int bf = st & 1;
        #pragma unroll
        for (int i = 0; i < 2; i++) {
            int e = tid + i * 256;
            int r = e >> 3, g = e & 7;
            CP_ASYNC16(sKu[bf] + SWZ128(r * 128 + g * 16),
                       kbase + (size_t)(st*64 + r) * HD + g * 8);
            CP_ASYNC16(sVu[bf] + SWZ128(r * 128 + g * 16),
                       vbase + (size_t)(st*64 + r) * HD + g * 8);
        }
    };
    issueKV(0); CP_COMMIT();

    float o[8][4] = {};
    float mrow[2] = {-1e30f, -1e30f};
    float lrow[2] = {};
    int lastTile = qt2 * 2 + (wid >> 2);
    int ntiles = qt2 * 2 + 2;

    for (int st = 0; st < ntiles; st++) {
        if (st < ntiles - 1) { issueKV(st + 1); CP_COMMIT(); CP_WAIT1(); }
        else                 { CP_WAIT0(); }
        __syncthreads();
        int bf = st & 1;

        if (st <= lastTile) {
            float sacc[8][4] = {};
            #pragma unroll
            for (int ks = 0; ks < 4; ks++) {
                uint32_t b[8][2];
                int col16 = ks * 2 + (lane >> 4);
                #pragma unroll
                for (int np = 0; np < 4; np++) {
                    int n = np * 16 + (lane & 15);
                    ldsm_x4(b[np*2][0], b[np*2+1][0], b[np*2][1], b[np*2+1][1],
                            sKu[bf] + SWZ128(n * 128 + col16 * 16));
                }
                #pragma unroll
                for (int nb = 0; nb < 8; nb++)
                    mma16816(sacc[nb], qf[ks][0], qf[ks][1], qf[ks][2], qf[ks][3],
                             b[nb][0], b[nb][1]);
            }

            if (st == lastTile) {
                int r0 = qt2*128 + wid*16 + (lane >> 2);
                #pragma unroll
                for (int nb = 0; nb < 8; nb++) {
                    int cg = st*64 + nb*8 + (lane & 3) * 2;
                    if (cg     > r0    ) sacc[nb][0] = -1e30f;
                    if (cg + 1 > r0    ) sacc[nb][1] = -1e30f;
                    if (cg     > r0 + 8) sacc[nb][2] = -1e30f;
                    if (cg + 1 > r0 + 8) sacc[nb][3] = -1e30f;
                }
            }

            #pragma unroll
            for (int hf = 0; hf < 2; hf++) {
                float mx = -1e30f;
                #pragma unroll
                for (int nb = 0; nb < 8; nb++)
                    mx = fmaxf(mx, fmaxf(sacc[nb][hf*2], sacc[nb][hf*2+1]));
                mx = fmaxf(mx, __shfl_xor_sync(0xffffffffu, mx, 1));
                mx = fmaxf(mx, __shfl_xor_sync(0xffffffffu, mx, 2));
                float mnew = fmaxf(mrow[hf], mx);
                float corr = __expf(mrow[hf] - mnew);
                float rs = 0.f;
                #pragma unroll
                for (int nb = 0; nb < 8; nb++) {
                    float p0 = __expf(sacc[nb][hf*2]   - mnew);
                    float p1 = __expf(sacc[nb][hf*2+1] - mnew);
                    sacc[nb][hf*2] = p0; sacc[nb][hf*2+1] = p1;
                    rs += p0 + p1;
                }
                rs += __shfl_xor_sync(0xffffffffu, rs, 1);
                rs += __shfl_xor_sync(0xffffffffu, rs, 2);
                lrow[hf] = lrow[hf] * corr + rs;
                mrow[hf] = mnew;
                #pragma unroll
                for (int nb = 0; nb < 8; nb++) {
                    o[nb][hf*2]   *= corr;
                    o[nb][hf*2+1] *= corr;
                }
            }

            #pragma unroll
            for (int ks = 0; ks < 4; ks++) {
                uint32_t pa0 = f2h2(sacc[ks*2  ][0], sacc[ks*2  ][1]);
                uint32_t pa1 = f2h2(sacc[ks*2  ][2], sacc[ks*2  ][3]);
                uint32_t pa2 = f2h2(sacc[ks*2+1][0], sacc[ks*2+1][1]);
                uint32_t pa3 = f2h2(sacc[ks*2+1][2], sacc[ks*2+1][3]);
                #pragma unroll
                for (int np = 0; np < 4; np++) {
                    int m = lane >> 3;
                    int row = ks * 16 + ((m & 1) << 3) + (lane & 7);
                    int colb = (np * 16 + ((m & 2) << 2)) * 2;
                    uint32_t v0, v1, v2, v3;
                    ldsm_x4_t(v0, v1, v2, v3, sVu[bf] + SWZ128(row * 128 + colb));
                    mma16816(o[np*2],   pa0, pa1, pa2, pa3, v0, v1);
                    mma16816(o[np*2+1], pa0, pa1, pa2, pa3, v2, v3);
                }
            }
        }
        __syncthreads();
    }

    float inv0 = 1.0f / lrow[0], inv1 = 1.0f / lrow[1];
    int t0 = qt2*128 + wid*16 + (lane >> 2);
    __half* ob = g_att16 + ((size_t)bh * NT + t0) * HD;
    #pragma unroll
    for (int nb = 0; nb < 8; nb++) {
        int n = nb*8 + (lane & 3) * 2;
        *(uint32_t*)(ob + n)        = f2h2(o[nb][0]*inv0, o[nb][1]*inv0);
        *(uint32_t*)(ob + 8*HD + n) = f2h2(o[nb][2]*inv1, o[nb][3]*inv1);
    }
}

// ===========================================================================
// Kernel 3: output projection + bias. grid (256, 6), block 128 (4 warps).
// CTA tile 64m x 64n; warp tile 16m x 64n (1 A-ldsm + 4 B-ldsm per 16 MMA).
// K = 6 chunks of 64 (one head each), cp.async double-buffered (32KB smem).
// 1536 CTAs -> high residency for latency hiding.
// ===========================================================================
__global__ __launch_bounds__(128) void proj_tc_kernel(
    const float* __restrict__ bp, float* __restrict__ out)
{
    __shared__ __align__(1024) __half smA[2][64*64];
    __shared__ __align__(1024) __half smB[2][64*64];

    int tid = threadIdx.x;
    int wid = tid >> 5, lane = tid & 31;
    int m0 = blockIdx.x * 64;
    int e0 = blockIdx.y * 64;
    int b  = m0 >> 8;
    int t0 = m0 & 255;

    const uint32_t sAu[2] = {smem_u32(smA[0]), smem_u32(smA[1])};
    const uint32_t sBu[2] = {smem_u32(smB[0]), smem_u32(smB[1])};

    float acc[8][4] = {};

    auto issue = [&](int hc) {
        int bf = hc & 1;
        const __half* abase = g_att16 + ((size_t)(b * NH + hc) * NT + t0) * HD;
        #pragma unroll
        for (int i = 0; i < 4; i++) {
            int e = tid + i * 128;
            int r = e >> 3, g = e & 7;
            CP_ASYNC16(sAu[bf] + SWZ128(r * 128 + g * 16),
                       abase + (size_t)r * HD + g * 8);
            CP_ASYNC16(sBu[bf] + SWZ128(r * 128 + g * 16),
                       g_wp16 + (size_t)(e0 + r) * 384 + hc * 64 + g * 8);
        }
    };

    issue(0); CP_COMMIT();
    for (int hc = 0; hc < 6; hc++) {
        if (hc < 5) { issue(hc + 1); CP_COMMIT(); CP_WAIT1(); }
        else        { CP_WAIT0(); }
        __syncthreads();
        int bf = hc & 1;
        #pragma unroll
        for (int ks = 0; ks < 4; ks++) {
            int col16 = ks * 2 + (lane >> 4);
            uint32_t a0, a1, a2, a3;
            {
                int row = wid * 16 + (lane & 15);
                ldsm_x4(a0, a1, a2, a3, sAu[bf] + SWZ128(row * 128 + col16 * 16));
            }
            uint32_t bb[8][2];
            #pragma unroll
            for (int np = 0; np < 4; np++) {
                int n = np * 16 + (lane & 15);
                ldsm_x4(bb[np*2][0], bb[np*2+1][0], bb[np*2][1], bb[np*2+1][1],
                        sBu[bf] + SWZ128(n * 128 + col16 * 16));
            }
            #pragma unroll
            for (int nb = 0; nb < 8; nb++)
                mma16816(acc[nb], a0, a1, a2, a3, bb[nb][0], bb[nb][1]);
        }
        __syncthreads();
    }

    int mg = m0 + wid * 16 + (lane >> 2);
    float* orow = out + (size_t)mg * NC + e0;
    #pragma unroll
    for (int nb = 0; nb < 8; nb++) {
        int n = nb * 8 + (lane & 3) * 2;
        float2 bb2 = *(const float2*)(bp + e0 + n);
        *(float2*)(orow + n) =
            make_float2(acc[nb][0] + bb2.x, acc[nb][1] + bb2.y);
        *(float2*)(orow + 8*NC + n) =
            make_float2(acc[nb][2] + bb2.x, acc[nb][3] + bb2.y);
    }
}

// ---------------------------------------------------------------------------

extern "C" void kernel_launch(void* const* d_in, const int* in_sizes, int n_in,
                              void* d_out, int out_size)
{
    const float* x  = (const float*)d_in[0];
    const float* Wq = (const float*)d_in[1];
    const float* Wk = (const float*)d_in[2];
    const float* Wv = (const float*)d_in[3];
    const float* Wp = (const float*)d_in[4];
    const float* bp = (const float*)d_in[5];
    float* out = (float*)d_out;

    convert_all_kernel<<<3096, 256>>>(x, Wq, Wk, Wv, Wp);
    qkv_tc_kernel<<<dim3(NM/128, NH), 384>>>();
    attn_tc_kernel<<<dim3(2, NB*NH), 256>>>();
    proj_tc_kernel<<<dim3(NM/64, NC/64), 128>>>(bp, out);
}

// round 13
// speedup vs baseline: 1.2451x; 1.1706x over previous
#include <cuda_runtime.h>
#include <cuda_fp16.h>
#include <cstdint>

#define NC 384
#define NH 6
#define HD 64
#define NB 64
#define NT 256
#define NM (NB*NT)
#define SOFT_SCALE 0.125f

// fp16 scratch (allocation-free rule: __device__ globals)
__device__ __align__(128) __half g_x16[(size_t)NM*NC];
__device__ __align__(128) __half g_wqkv16[(size_t)NH*3*HD*NC];  // [h][mat][n=64][k=384]
__device__ __align__(128) __half g_wp16[(size_t)NC*NC];         // [n=384][k=384]
__device__ __align__(128) __half g_att16[(size_t)NB*NH*NT*HD];

#define SWZ128(b) ((b) ^ (((b) >> 3) & 0x70))

static __device__ __forceinline__ uint32_t smem_u32(const void* p) {
    uint32_t a;
    asm("{ .reg .u64 t; cvta.to.shared.u64 t, %1; cvt.u32.u64 %0, t; }"
        : "=r"(a) : "l"(p));
    return a;
}
static __device__ __forceinline__ void ldsm_x4(
    uint32_t& r0, uint32_t& r1, uint32_t& r2, uint32_t& r3, uint32_t addr)
{
    asm volatile("ldmatrix.sync.aligned.m8n8.x4.shared.b16 {%0,%1,%2,%3}, [%4];"
                 : "=r"(r0), "=r"(r1), "=r"(r2), "=r"(r3) : "r"(addr));
}
static __device__ __forceinline__ void ldsm_x4_t(
    uint32_t& r0, uint32_t& r1, uint32_t& r2, uint32_t& r3, uint32_t addr)
{
    asm volatile("ldmatrix.sync.aligned.m8n8.x4.trans.shared.b16 {%0,%1,%2,%3}, [%4];"
                 : "=r"(r0), "=r"(r1), "=r"(r2), "=r"(r3) : "r"(addr));
}
static __device__ __forceinline__ void mma16816(
    float* c, uint32_t a0, uint32_t a1, uint32_t a2, uint32_t a3,
    uint32_t b0, uint32_t b1)
{
    asm volatile(
        "mma.sync.aligned.m16n8k16.row.col.f32.f16.f16.f32 "
        "{%0,%1,%2,%3}, {%4,%5,%6,%7}, {%8,%9}, {%0,%1,%2,%3};"
        : "+f"(c[0]), "+f"(c[1]), "+f"(c[2]), "+f"(c[3])
        : "r"(a0), "r"(a1), "r"(a2), "r"(a3), "r"(b0), "r"(b1));
}
static __device__ __forceinline__ uint32_t f2h2(float a, float b) {
    __half2 h = __floats2half2_rn(a, b);
    return *reinterpret_cast<uint32_t*>(&h);
}
#define CP_ASYNC16(d, s) \
    asm volatile("cp.async.ca.shared.global [%0], [%1], 16;" :: "r"(d), "l"(s))
#define CP_COMMIT() asm volatile("cp.async.commit_group;" ::: "memory")
#define CP_WAIT0()  asm volatile("cp.async.wait_group 0;" ::: "memory")
#define CP_WAIT1()  asm volatile("cp.async.wait_group 1;" ::: "memory")

// ===========================================================================
// Prologue: converts. blocks [0,3072): x -> fp16. blocks [3072,3096): weights.
// ===========================================================================
__global__ __launch_bounds__(256) void convert_all_kernel(
    const float* __restrict__ x,
    const float* __restrict__ Wq, const float* __restrict__ Wk,
    const float* __restrict__ Wv, const float* __restrict__ Wp)
{
    __shared__ __half tw[64 * 384];
    int tid = threadIdx.x;

    if (blockIdx.x < 3072) {
        size_t i = ((size_t)blockIdx.x * 256 + tid) * 8;
        float4 u = *(const float4*)(x + i);
        float4 v = *(const float4*)(x + i + 4);
        *(uint4*)(g_x16 + i) = make_uint4(f2h2(u.x,u.y), f2h2(u.z,u.w),
                                          f2h2(v.x,v.y), f2h2(v.z,v.w));
        return;
    }
    int blk = blockIdx.x - 3072;
    if (blk < 18) {
        const float* Wsrcs[3] = {Wq, Wk, Wv};
        int mat = blk / 6, h = blk % 6;
        const float* W = Wsrcs[mat] + (size_t)h * NC * HD;
        for (int e = tid; e < 384 * 16; e += 256) {
            int k = e >> 4, n4 = e & 15;
            float4 w = *(const float4*)(W + (size_t)k * HD + n4 * 4);
            tw[(n4*4+0) * 384 + k] = __float2half_rn(w.x);
            tw[(n4*4+1) * 384 + k] = __float2half_rn(w.y);
            tw[(n4*4+2) * 384 + k] = __float2half_rn(w.z);
            tw[(n4*4+3) * 384 + k] = __float2half_rn(w.w);
        }
        __syncthreads();
        uint4* dst = (uint4*)(g_wqkv16 + (size_t)(h * 3 + mat) * 64 * 384);
        for (int e = tid; e < 64 * 48; e += 256)
            dst[e] = *(uint4*)(tw + e * 8);
    } else {
        int n0 = (blk - 18) * 64;
        for (int e = tid; e < 384 * 16; e += 256) {
            int k = e >> 4, n4 = e & 15;
            float4 w = *(const float4*)(Wp + (size_t)k * NC + n0 + n4 * 4);
            tw[(n4*4+0) * 384 + k] = __float2half_rn(w.x);
            tw[(n4*4+1) * 384 + k] = __float2half_rn(w.y);
            tw[(n4*4+2) * 384 + k] = __float2half_rn(w.z);
            tw[(n4*4+3) * 384 + k] = __float2half_rn(w.w);
        }
        __syncthreads();
        uint4* dst = (uint4*)(g_wp16 + (size_t)n0 * 384);
        for (int e = tid; e < 64 * 48; e += 256)
            dst[e] = *(uint4*)(tw + e * 8);
    }
}

// ===========================================================================
// Fused QKV-GEMM + causal flash attention. grid (NH, NB), block 256 (8 warps).
// Dynamic smem (176KB):
//   [0,32K)      Qs  [256 t][64 d] fp16, pre-scaled
//   [32K,64K)    Ks  [256 t][64 d]
//   [64K,96K)    Vs  [256 t][64 d]
//   [96K,128K)   Astage x2 (128 m x 64 k fp16 each)
//   [128K,176K)  Bstage x2 (192 n x 64 k fp16 each)
// Phase 1: two 128-row passes; warp = 16m x 192n (acc[24][4]); cp.async
//   double-buffered K-chunks of 64; epilogue stores fp16 into Qs/Ks/Vs.
// Phase 2: attention, K/V smem-resident; warp = 16 q-rows x 2 sub-passes.
// ===========================================================================
#define QS_OFF   0
#define KS_OFF   32768
#define VS_OFF   65536
#define AST_OFF  98304
#define BST_OFF  131072
#define FUSED_SMEM (131072 + 2*24576)   // 180224

extern __shared__ unsigned char sm_fused[];

__global__ __launch_bounds__(256) void qkv_attn_kernel()
{
    int tid = threadIdx.x;
    int wid = tid >> 5, lane = tid & 31;
    int h = blockIdx.x;
    int b = blockIdx.y;

    const uint32_t sQ = smem_u32(sm_fused) + QS_OFF;
    const uint32_t sK = smem_u32(sm_fused) + KS_OFF;
    const uint32_t sV = smem_u32(sm_fused) + VS_OFF;
    const uint32_t sA[2] = {smem_u32(sm_fused) + AST_OFF,
                            smem_u32(sm_fused) + AST_OFF + 16384};
    const uint32_t sB[2] = {smem_u32(sm_fused) + BST_OFF,
                            smem_u32(sm_fused) + BST_OFF + 24576};

    const __half* xsrc = g_x16 + (size_t)b * NT * NC;
    const __half* wsrc = g_wqkv16 + (size_t)h * 192 * 384;

    // ---------------- Phase 1: Q|K|V GEMM ----------------
    for (int pass = 0; pass < 2; pass++) {
        float acc[24][4] = {};

        auto issue = [&](int c) {
            int c0 = c * 64, bf = c & 1;
            #pragma unroll
            for (int i = 0; i < 4; i++) {            // A: 1024 items
                int e = tid + i * 256;
                int r = e >> 3, g = e & 7;
                CP_ASYNC16(sA[bf] + SWZ128(r * 128 + g * 16),
                           xsrc + (size_t)(pass * 128 + r) * NC + c0 + g * 8);
            }
            #pragma unroll
            for (int i = 0; i < 6; i++) {            // B: 1536 items
                int e = tid + i * 256;
                int n = e >> 3, g = e & 7;
                CP_ASYNC16(sB[bf] + SWZ128(n * 128 + g * 16),
                           wsrc + (size_t)n * 384 + c0 + g * 8);
            }
        };

        issue(0); CP_COMMIT();
        for (int c = 0; c < 6; c++) {
            if (c < 5) { issue(c + 1); CP_COMMIT(); CP_WAIT1(); }
            else       { CP_WAIT0(); }
            __syncthreads();
            int bf = c & 1;
            #pragma unroll
            for (int ks = 0; ks < 4; ks++) {
                int col16 = ks * 2 + (lane >> 4);
                uint32_t a0, a1, a2, a3;
                {
                    int row = wid * 16 + (lane & 15);
                    ldsm_x4(a0, a1, a2, a3, sA[bf] + SWZ128(row * 128 + col16 * 16));
                }
                #pragma unroll
                for (int nb16 = 0; nb16 < 12; nb16++) {
                    int n = nb16 * 16 + (lane & 15);
                    uint32_t b0a, b0b, b1a, b1b;
                    ldsm_x4(b0a, b0b, b1a, b1b, sB[bf] + SWZ128(n * 128 + col16 * 16));
                    mma16816(acc[nb16*2],   a0, a1, a2, a3, b0a, b1a);
                    mma16816(acc[nb16*2+1], a0, a1, a2, a3, b0b, b1b);
                }
            }
            __syncthreads();
        }

        // epilogue: store 16 rows x 192 cols to Qs/Ks/Vs (Q scaled)
        unsigned char* smb = sm_fused;
        int r0 = wid * 16 + (lane >> 2);
        int t0 = pass * 128 + r0;
        #pragma unroll
        for (int nb = 0; nb < 24; nb++) {
            int mat = nb >> 3;
            int col = (nb & 7) * 8 + (lane & 3) * 2;
            float sc = (mat == 0) ? SOFT_SCALE : 1.0f;
            int base = (mat == 0 ? QS_OFF : (mat == 1 ? KS_OFF : VS_OFF));
            *(uint32_t*)(smb + base + SWZ128(t0 * 128 + col * 2)) =
                f2h2(acc[nb][0]*sc, acc[nb][1]*sc);
            *(uint32_t*)(smb + base + SWZ128((t0 + 8) * 128 + col * 2)) =
                f2h2(acc[nb][2]*sc, acc[nb][3]*sc);
        }
    }
    __syncthreads();   // all Q/K/V in smem

    // ---------------- Phase 2: causal attention ----------------
    __half* obase = g_att16 + ((size_t)(b * NH + h) * NT) * HD;

    #pragma unroll
    for (int p2 = 0; p2 < 2; p2++) {
        int R = p2 * 128 + wid * 16;

        uint32_t qf[4][4];
        #pragma unroll
        for (int ks = 0; ks < 4; ks++) {
            int col16 = ks * 2 + (lane >> 4);
            ldsm_x4(qf[ks][0], qf[ks][1], qf[ks][2], qf[ks][3],
                    sQ + SWZ128((R + (lane & 15)) * 128 + col16 * 16));
        }

        float o[8][4] = {};
        float mrow[2] = {-1e30f, -1e30f};
        float lrow[2] = {};
        int lt = (R + 15) >> 6;

        for (int st = 0; st <= lt; st++) {
            // S = Q K^T
            float sacc[8][4] = {};
            #pragma unroll
            for (int ks = 0; ks < 4; ks++) {
                int col16 = ks * 2 + (lane >> 4);
                #pragma unroll
                for (int np = 0; np < 4; np++) {
                    int n = st * 64 + np * 16 + (lane & 15);
                    uint32_t b0a, b0b, b1a, b1b;
                    ldsm_x4(b0a, b0b, b1a, b1b, sK + SWZ128(n * 128 + col16 * 16));
                    mma16816(sacc[np*2],   qf[ks][0], qf[ks][1], qf[ks][2], qf[ks][3], b0a, b1a);
                    mma16816(sacc[np*2+1], qf[ks][0], qf[ks][1], qf[ks][2], qf[ks][3], b0b, b1b);
                }
            }

            if (st == lt) {
                int r0 = R + (lane >> 2);
                #pragma unroll
                for (int nb = 0; nb < 8; nb++) {
                    int cg = st*64 + nb*8 + (lane & 3) * 2;
                    if (cg     > r0    ) sacc[nb][0] = -1e30f;
                    if (cg + 1 > r0    ) sacc[nb][1] = -1e30f;
                    if (cg     > r0 + 8) sacc[nb][2] = -1e30f;
                    if (cg + 1 > r0 + 8) sacc[nb][3] = -1e30f;
                }
            }

            #pragma unroll
            for (int hf = 0; hf < 2; hf++) {
                float mx = -1e30f;
                #pragma unroll
                for (int nb = 0; nb < 8; nb++)
                    mx = fmaxf(mx, fmaxf(sacc[nb][hf*2], sacc[nb][hf*2+1]));
                mx = fmaxf(mx, __shfl_xor_sync(0xffffffffu, mx, 1));
                mx = fmaxf(mx, __shfl_xor_sync(0xffffffffu, mx, 2));
                float mnew = fmaxf(mrow[hf], mx);
                float corr = __expf(mrow[hf] - mnew);
                float rs = 0.f;
                #pragma unroll
                for (int nb = 0; nb < 8; nb++) {
                    float p0 = __expf(sacc[nb][hf*2]   - mnew);
                    float p1 = __expf(sacc[nb][hf*2+1] - mnew);
                    sacc[nb][hf*2] = p0; sacc[nb][hf*2+1] = p1;
                    rs += p0 + p1;
                }
                rs += __shfl_xor_sync(0xffffffffu, rs, 1);
                rs += __shfl_xor_sync(0xffffffffu, rs, 2);
                lrow[hf] = lrow[hf] * corr + rs;
                mrow[hf] = mnew;
                #pragma unroll
                for (int nb = 0; nb < 8; nb++) {
                    o[nb][hf*2]   *= corr;
                    o[nb][hf*2+1] *= corr;
                }
            }

            // O += P V
            #pragma unroll
            for (int ks = 0; ks < 4; ks++) {
                uint32_t pa0 = f2h2(sacc[ks*2  ][0], sacc[ks*2  ][1]);
                uint32_t pa1 = f2h2(sacc[ks*2  ][2], sacc[ks*2  ][3]);
                uint32_t pa2 = f2h2(sacc[ks*2+1][0], sacc[ks*2+1][1]);
                uint32_t pa3 = f2h2(sacc[ks*2+1][2], sacc[ks*2+1][3]);
                #pragma unroll
                for (int np = 0; np < 4; np++) {
                    int m = lane >> 3;
                    int row = st * 64 + ks * 16 + ((m & 1) << 3) + (lane & 7);
                    int colb = (np * 16 + ((m & 2) << 2)) * 2;
                    uint32_t v0, v1, v2, v3;
                    ldsm_x4_t(v0, v1, v2, v3, sV + SWZ128(row * 128 + colb));
                    mma16816(o[np*2],   pa0, pa1, pa2, pa3, v0, v1);
                    mma16816(o[np*2+1], pa0, pa1, pa2, pa3, v2, v3);
                }
            }
        }

        float inv0 = 1.0f / lrow[0], inv1 = 1.0f / lrow[1];
        int t0 = R + (lane >> 2);
        __half* ob = obase + (size_t)t0 * HD;
        #pragma unroll
        for (int nb = 0; nb < 8; nb++) {
            int n = nb*8 + (lane & 3) * 2;
            *(uint32_t*)(ob + n)        = f2h2(o[nb][0]*inv0, o[nb][1]*inv0);
            *(uint32_t*)(ob + 8*HD + n) = f2h2(o[nb][2]*inv1, o[nb][3]*inv1);
        }
    }
}

// ===========================================================================
// Kernel 3: output projection + bias. grid (256, 6), block 128 (4 warps).
// (R12 version, unchanged)
// ===========================================================================
__global__ __launch_bounds__(128) void proj_tc_kernel(
    const float* __restrict__ bp, float* __restrict__ out)
{
    __shared__ __align__(1024) __half smA[2][64*64];
    __shared__ __align__(1024) __half smB[2][64*64];

    int tid = threadIdx.x;
    int wid = tid >> 5, lane = tid & 31;
    int m0 = blockIdx.x * 64;
    int e0 = blockIdx.y * 64;
    int b  = m0 >> 8;
    int t0 = m0 & 255;

    const uint32_t sAu[2] = {smem_u32(smA[0]), smem_u32(smA[1])};
    const uint32_t sBu[2] = {smem_u32(smB[0]), smem_u32(smB[1])};

    float acc[8][4] = {};

    auto issue = [&](int hc) {
        int bf = hc & 1;
        const __half* abase = g_att16 + ((size_t)(b * NH + hc) * NT + t0) * HD;
        #pragma unroll
        for (int i = 0; i < 4; i++) {
            int e = tid + i * 128;
            int r = e >> 3, g = e & 7;
            CP_ASYNC16(sAu[bf] + SWZ128(r * 128 + g * 16),
                       abase + (size_t)r * HD + g * 8);
            CP_ASYNC16(sBu[bf] + SWZ128(r * 128 + g * 16),
                       g_wp16 + (size_t)(e0 + r) * 384 + hc * 64 + g * 8);
        }
    };

    issue(0); CP_COMMIT();
    for (int hc = 0; hc < 6; hc++) {
        if (hc < 5) { issue(hc + 1); CP_COMMIT(); CP_WAIT1(); }
        else        { CP_WAIT0(); }
        __syncthreads();
        int bf = hc & 1;
        #pragma unroll
        for (int ks = 0; ks < 4; ks++) {
            int col16 = ks * 2 + (lane >> 4);
            uint32_t a0, a1, a2, a3;
            {
                int row = wid * 16 + (lane & 15);
                ldsm_x4(a0, a1, a2, a3, sAu[bf] + SWZ128(row * 128 + col16 * 16));
            }
            uint32_t bb[8][2];
            #pragma unroll
            for (int np = 0; np < 4; np++) {
                int n = np * 16 + (lane & 15);
                ldsm_x4(bb[np*2][0], bb[np*2+1][0], bb[np*2][1], bb[np*2+1][1],
                        sBu[bf] + SWZ128(n * 128 + col16 * 16));
            }
            #pragma unroll
            for (int nb = 0; nb < 8; nb++)
                mma16816(acc[nb], a0, a1, a2, a3, bb[nb][0], bb[nb][1]);
        }
        __syncthreads();
    }

    int mg = m0 + wid * 16 + (lane >> 2);
    float* orow = out + (size_t)mg * NC + e0;
    #pragma unroll
    for (int nb = 0; nb < 8; nb++) {
        int n = nb * 8 + (lane & 3) * 2;
        float2 bb2 = *(const float2*)(bp + e0 + n);
        *(float2*)(orow + n) =
            make_float2(acc[nb][0] + bb2.x, acc[nb][1] + bb2.y);
        *(float2*)(orow + 8*NC + n) =
            make_float2(acc[nb][2] + bb2.x, acc[nb][3] + bb2.y);
    }
}

// ---------------------------------------------------------------------------

extern "C" void kernel_launch(void* const* d_in, const int* in_sizes, int n_in,
                              void* d_out, int out_size)
{
    const float* x  = (const float*)d_in[0];
    const float* Wq = (const float*)d_in[1];
    const float* Wk = (const float*)d_in[2];
    const float* Wv = (const float*)d_in[3];
    const float* Wp = (const float*)d_in[4];
    const float* bp = (const float*)d_in[5];
    float* out = (float*)d_out;

    cudaFuncSetAttribute(qkv_attn_kernel,
                         cudaFuncAttributeMaxDynamicSharedMemorySize, FUSED_SMEM);

    convert_all_kernel<<<3096, 256>>>(x, Wq, Wk, Wv, Wp);
    qkv_attn_kernel<<<dim3(NH, NB), 256, FUSED_SMEM>>>();
    proj_tc_kernel<<<dim3(NM/64, NC/64), 128>>>(bp, out);
}

// round 15
// speedup vs baseline: 1.3034x; 1.0468x over previous
#include <cuda_runtime.h>
#include <cuda_fp16.h>
#include <cstdint>

#define NC 384
#define NH 6
#define HD 64
#define NB 64
#define NT 256
#define NM (NB*NT)
#define SOFT_SCALE 0.125f

// fp16 scratch (allocation-free rule: __device__ globals)
__device__ __align__(128) __half g_x16[(size_t)NM*NC];
__device__ __align__(128) __half g_wqkv16[(size_t)NH*3*HD*NC];  // [h][mat][n=64][k=384]
__device__ __align__(128) __half g_wp16[(size_t)NC*NC];         // [n=384][k=384]
__device__ __align__(128) __half g_att16[(size_t)NB*NH*NT*HD];

#define SWZ128(b) ((b) ^ (((b) >> 3) & 0x70))

static __device__ __forceinline__ uint32_t smem_u32(const void* p) {
    uint32_t a;
    asm("{ .reg .u64 t; cvta.to.shared.u64 t, %1; cvt.u32.u64 %0, t; }"
        : "=r"(a) : "l"(p));
    return a;
}
static __device__ __forceinline__ void ldsm_x4(
    uint32_t& r0, uint32_t& r1, uint32_t& r2, uint32_t& r3, uint32_t addr)
{
    asm volatile("ldmatrix.sync.aligned.m8n8.x4.shared.b16 {%0,%1,%2,%3}, [%4];"
                 : "=r"(r0), "=r"(r1), "=r"(r2), "=r"(r3) : "r"(addr));
}
static __device__ __forceinline__ void ldsm_x4_t(
    uint32_t& r0, uint32_t& r1, uint32_t& r2, uint32_t& r3, uint32_t addr)
{
    asm volatile("ldmatrix.sync.aligned.m8n8.x4.trans.shared.b16 {%0,%1,%2,%3}, [%4];"
                 : "=r"(r0), "=r"(r1), "=r"(r2), "=r"(r3) : "r"(addr));
}
static __device__ __forceinline__ void mma16816(
    float* c, uint32_t a0, uint32_t a1, uint32_t a2, uint32_t a3,
    uint32_t b0, uint32_t b1)
{
    asm volatile(
        "mma.sync.aligned.m16n8k16.row.col.f32.f16.f16.f32 "
        "{%0,%1,%2,%3}, {%4,%5,%6,%7}, {%8,%9}, {%0,%1,%2,%3};"
        : "+f"(c[0]), "+f"(c[1]), "+f"(c[2]), "+f"(c[3])
        : "r"(a0), "r"(a1), "r"(a2), "r"(a3), "r"(b0), "r"(b1));
}
static __device__ __forceinline__ uint32_t f2h2(float a, float b) {
    __half2 h = __floats2half2_rn(a, b);
    return *reinterpret_cast<uint32_t*>(&h);
}
#define CP_ASYNC16(d, s) \
    asm volatile("cp.async.ca.shared.global [%0], [%1], 16;" :: "r"(d), "l"(s))
#define CP_COMMIT() asm volatile("cp.async.commit_group;" ::: "memory")
#define CP_WAIT0()  asm volatile("cp.async.wait_group 0;" ::: "memory")
#define CP_WAIT1()  asm volatile("cp.async.wait_group 1;" ::: "memory")

// ===========================================================================
// Prologue: converts.
// blocks [0,768): x -> fp16, 32 floats/thread, 8 independent LDG.128 (MLP=8).
// blocks [768,792): weights -> fp16 transposed to [n][k].
// ===========================================================================
__global__ __launch_bounds__(256) void convert_all_kernel(
    const float* __restrict__ x,
    const float* __restrict__ Wq, const float* __restrict__ Wk,
    const float* __restrict__ Wv, const float* __restrict__ Wp)
{
    __shared__ __half tw[64 * 384];
    int tid = threadIdx.x;

    if (blockIdx.x < 768) {
        size_t base = (size_t)blockIdx.x * 8192;   // 256 thr * 32 floats
        float4 u[8];
        #pragma unroll
        for (int i = 0; i < 8; i++)
            u[i] = *(const float4*)(x + base + (size_t)i * 1024 + tid * 4);
        #pragma unroll
        for (int i = 0; i < 8; i++) {
            uint2 pk = make_uint2(f2h2(u[i].x, u[i].y), f2h2(u[i].z, u[i].w));
            *(uint2*)(g_x16 + base + (size_t)i * 1024 + tid * 4) = pk;
        }
        return;
    }
    int blk = blockIdx.x - 768;
    if (blk < 18) {
        const float* Wsrcs[3] = {Wq, Wk, Wv};
        int mat = blk / 6, h = blk % 6;
        const float* W = Wsrcs[mat] + (size_t)h * NC * HD;
        for (int e = tid; e < 384 * 16; e += 256) {
            int k = e >> 4, n4 = e & 15;
            float4 w = *(const float4*)(W + (size_t)k * HD + n4 * 4);
            tw[(n4*4+0) * 384 + k] = __float2half_rn(w.x);
            tw[(n4*4+1) * 384 + k] = __float2half_rn(w.y);
            tw[(n4*4+2) * 384 + k] = __float2half_rn(w.z);
            tw[(n4*4+3) * 384 + k] = __float2half_rn(w.w);
        }
        __syncthreads();
        uint4* dst = (uint4*)(g_wqkv16 + (size_t)(h * 3 + mat) * 64 * 384);
        for (int e = tid; e < 64 * 48; e += 256)
            dst[e] = *(uint4*)(tw + e * 8);
    } else {
        int n0 = (blk - 18) * 64;
        for (int e = tid; e < 384 * 16; e += 256) {
            int k = e >> 4, n4 = e & 15;
            float4 w = *(const float4*)(Wp + (size_t)k * NC + n0 + n4 * 4);
            tw[(n4*4+0) * 384 + k] = __float2half_rn(w.x);
            tw[(n4*4+1) * 384 + k] = __float2half_rn(w.y);
            tw[(n4*4+2) * 384 + k] = __float2half_rn(w.z);
            tw[(n4*4+3) * 384 + k] = __float2half_rn(w.w);
        }
        __syncthreads();
        uint4* dst = (uint4*)(g_wp16 + (size_t)n0 * 384);
        for (int e = tid; e < 64 * 48; e += 256)
            dst[e] = *(uint4*)(tw + e * 8);
    }
}

// ===========================================================================
// Fused QKV-GEMM + causal flash attention. grid (NH, NB), block 256 (8 warps).
// Dynamic smem (176KB). (R13 version, unchanged)
// ===========================================================================
#define QS_OFF   0
#define KS_OFF   32768
#define VS_OFF   65536
#define AST_OFF  98304
#define BST_OFF  131072
#define FUSED_SMEM (131072 + 2*24576)   // 180224

extern __shared__ unsigned char sm_fused[];

__global__ __launch_bounds__(256) void qkv_attn_kernel()
{
    int tid = threadIdx.x;
    int wid = tid >> 5, lane = tid & 31;
    int h = blockIdx.x;
    int b = blockIdx.y;

    const uint32_t sQ = smem_u32(sm_fused) + QS_OFF;
    const uint32_t sK = smem_u32(sm_fused) + KS_OFF;
    const uint32_t sV = smem_u32(sm_fused) + VS_OFF;
    const uint32_t sA[2] = {smem_u32(sm_fused) + AST_OFF,
                            smem_u32(sm_fused) + AST_OFF + 16384};
    const uint32_t sB[2] = {smem_u32(sm_fused) + BST_OFF,
                            smem_u32(sm_fused) + BST_OFF + 24576};

    const __half* xsrc = g_x16 + (size_t)b * NT * NC;
    const __half* wsrc = g_wqkv16 + (size_t)h * 192 * 384;

    // ---------------- Phase 1: Q|K|V GEMM ----------------
    for (int pass = 0; pass < 2; pass++) {
        float acc[24][4] = {};

        auto issue = [&](int c) {
            int c0 = c * 64, bf = c & 1;
            #pragma unroll
            for (int i = 0; i < 4; i++) {            // A: 1024 items
                int e = tid + i * 256;
                int r = e >> 3, g = e & 7;
                CP_ASYNC16(sA[bf] + SWZ128(r * 128 + g * 16),
                           xsrc + (size_t)(pass * 128 + r) * NC + c0 + g * 8);
            }
            #pragma unroll
            for (int i = 0; i < 6; i++) {            // B: 1536 items
                int e = tid + i * 256;
                int n = e >> 3, g = e & 7;
                CP_ASYNC16(sB[bf] + SWZ128(n * 128 + g * 16),
                           wsrc + (size_t)n * 384 + c0 + g * 8);
            }
        };

        issue(0); CP_COMMIT();
        for (int c = 0; c < 6; c++) {
            if (c < 5) { issue(c + 1); CP_COMMIT(); CP_WAIT1(); }
            else       { CP_WAIT0(); }
            __syncthreads();
            int bf = c & 1;
            #pragma unroll
            for (int ks = 0; ks < 4; ks++) {
                int col16 = ks * 2 + (lane >> 4);
                uint32_t a0, a1, a2, a3;
                {
                    int row = wid * 16 + (lane & 15);
                    ldsm_x4(a0, a1, a2, a3, sA[bf] + SWZ128(row * 128 + col16 * 16));
                }
                #pragma unroll
                for (int nb16 = 0; nb16 < 12; nb16++) {
                    int n = nb16 * 16 + (lane & 15);
                    uint32_t b0a, b0b, b1a, b1b;
                    ldsm_x4(b0a, b0b, b1a, b1b, sB[bf] + SWZ128(n * 128 + col16 * 16));
                    mma16816(acc[nb16*2],   a0, a1, a2, a3, b0a, b1a);
                    mma16816(acc[nb16*2+1], a0, a1, a2, a3, b0b, b1b);
                }
            }
            __syncthreads();
        }

        // epilogue: store 16 rows x 192 cols to Qs/Ks/Vs (Q scaled)
        unsigned char* smb = sm_fused;
        int r0 = wid * 16 + (lane >> 2);
        int t0 = pass * 128 + r0;
        #pragma unroll
        for (int nb = 0; nb < 24; nb++) {
            int mat = nb >> 3;
            int col = (nb & 7) * 8 + (lane & 3) * 2;
            float sc = (mat == 0) ? SOFT_SCALE : 1.0f;
            int base = (mat == 0 ? QS_OFF : (mat == 1 ? KS_OFF : VS_OFF));
            *(uint32_t*)(smb + base + SWZ128(t0 * 128 + col * 2)) =
                f2h2(acc[nb][0]*sc, acc[nb][1]*sc);
            *(uint32_t*)(smb + base + SWZ128((t0 + 8) * 128 + col * 2)) =
                f2h2(acc[nb][2]*sc, acc[nb][3]*sc);
        }
    }
    __syncthreads();   // all Q/K/V in smem

    // ---------------- Phase 2: causal attention ----------------
    __half* obase = g_att16 + ((size_t)(b * NH + h) * NT) * HD;

    #pragma unroll
    for (int p2 = 0; p2 < 2; p2++) {
        int R = p2 * 128 + wid * 16;

        uint32_t qf[4][4];
        #pragma unroll
        for (int ks = 0; ks < 4; ks++) {
            int col16 = ks * 2 + (lane >> 4);
            ldsm_x4(qf[ks][0], qf[ks][1], qf[ks][2], qf[ks][3],
                    sQ + SWZ128((R + (lane & 15)) * 128 + col16 * 16));
        }

        float o[8][4] = {};
        float mrow[2] = {-1e30f, -1e30f};
        float lrow[2] = {};
        int lt = (R + 15) >> 6;

        for (int st = 0; st <= lt; st++) {
            // S = Q K^T
            float sacc[8][4] = {};
            #pragma unroll
            for (int ks = 0; ks < 4; ks++) {
                int col16 = ks * 2 + (lane >> 4);
                #pragma unroll
                for (int np = 0; np < 4; np++) {
                    int n = st * 64 + np * 16 + (lane & 15);
                    uint32_t b0a, b0b, b1a, b1b;
                    ldsm_x4(b0a, b0b, b1a, b1b, sK + SWZ128(n * 128 + col16 * 16));
                    mma16816(sacc[np*2],   qf[ks][0], qf[ks][1], qf[ks][2], qf[ks][3], b0a, b1a);
                    mma16816(sacc[np*2+1], qf[ks][0], qf[ks][1], qf[ks][2], qf[ks][3], b0b, b1b);
                }
            }

            if (st == lt) {
                int r0 = R + (lane >> 2);
                #pragma unroll
                for (int nb = 0; nb < 8; nb++) {
                    int cg = st*64 + nb*8 + (lane & 3) * 2;
                    if (cg     > r0    ) sacc[nb][0] = -1e30f;
                    if (cg + 1 > r0    ) sacc[nb][1] = -1e30f;
                    if (cg     > r0 + 8) sacc[nb][2] = -1e30f;
                    if (cg + 1 > r0 + 8) sacc[nb][3] = -1e30f;
                }
            }

            #pragma unroll
            for (int hf = 0; hf < 2; hf++) {
                float mx = -1e30f;
                #pragma unroll
                for (int nb = 0; nb < 8; nb++)
                    mx = fmaxf(mx, fmaxf(sacc[nb][hf*2], sacc[nb][hf*2+1]));
                mx = fmaxf(mx, __shfl_xor_sync(0xffffffffu, mx, 1));
                mx = fmaxf(mx, __shfl_xor_sync(0xffffffffu, mx, 2));
                float mnew = fmaxf(mrow[hf], mx);
                float corr = __expf(mrow[hf] - mnew);
                float rs = 0.f;
                #pragma unroll
                for (int nb = 0; nb < 8; nb++) {
                    float p0 = __expf(sacc[nb][hf*2]   - mnew);
                    float p1 = __expf(sacc[nb][hf*2+1] - mnew);
                    sacc[nb][hf*2] = p0; sacc[nb][hf*2+1] = p1;
                    rs += p0 + p1;
                }
                rs += __shfl_xor_sync(0xffffffffu, rs, 1);
                rs += __shfl_xor_sync(0xffffffffu, rs, 2);
                lrow[hf] = lrow[hf] * corr + rs;
                mrow[hf] = mnew;
                #pragma unroll
                for (int nb = 0; nb < 8; nb++) {
                    o[nb][hf*2]   *= corr;
                    o[nb][hf*2+1] *= corr;
                }
            }

            // O += P V
            #pragma unroll
            for (int ks = 0; ks < 4; ks++) {
                uint32_t pa0 = f2h2(sacc[ks*2  ][0], sacc[ks*2  ][1]);
                uint32_t pa1 = f2h2(sacc[ks*2  ][2], sacc[ks*2  ][3]);
                uint32_t pa2 = f2h2(sacc[ks*2+1][0], sacc[ks*2+1][1]);
                uint32_t pa3 = f2h2(sacc[ks*2+1][2], sacc[ks*2+1][3]);
                #pragma unroll
                for (int np = 0; np < 4; np++) {
                    int m = lane >> 3;
                    int row = st * 64 + ks * 16 + ((m & 1) << 3) + (lane & 7);
                    int colb = (np * 16 + ((m & 2) << 2)) * 2;
                    uint32_t v0, v1, v2, v3;
                    ldsm_x4_t(v0, v1, v2, v3, sV + SWZ128(row * 128 + colb));
                    mma16816(o[np*2],   pa0, pa1, pa2, pa3, v0, v1);
                    mma16816(o[np*2+1], pa0, pa1, pa2, pa3, v2, v3);
                }
            }
        }

        float inv0 = 1.0f / lrow[0], inv1 = 1.0f / lrow[1];
        int t0 = R + (lane >> 2);
        __half* ob = obase + (size_t)t0 * HD;
        #pragma unroll
        for (int nb = 0; nb < 8; nb++) {
            int n = nb*8 + (lane & 3) * 2;
            *(uint32_t*)(ob + n)        = f2h2(o[nb][0]*inv0, o[nb][1]*inv0);
            *(uint32_t*)(ob + 8*HD + n) = f2h2(o[nb][2]*inv1, o[nb][3]*inv1);
        }
    }
}

// ===========================================================================
// Kernel 3: output projection + bias. grid (256, 6), block 128 (4 warps).
// (unchanged)
// ===========================================================================
__global__ __launch_bounds__(128) void proj_tc_kernel(
    const float* __restrict__ bp, float* __restrict__ out)
{
    __shared__ __align__(1024) __half smA[2][64*64];
    __shared__ __align__(1024) __half smB[2][64*64];

    int tid = threadIdx.x;
    int wid = tid >> 5, lane = tid & 31;
    int m0 = blockIdx.x * 64;
    int e0 = blockIdx.y * 64;
    int b  = m0 >> 8;
    int t0 = m0 & 255;

    const uint32_t sAu[2] = {smem_u32(smA[0]), smem_u32(smA[1])};
    const uint32_t sBu[2] = {smem_u32(smB[0]), smem_u32(smB[1])};

    float acc[8][4] = {};

    auto issue = [&](int hc) {
        int bf = hc & 1;
        const __half* abase = g_att16 + ((size_t)(b * NH + hc) * NT + t0) * HD;
        #pragma unroll
        for (int i = 0; i < 4; i++) {
            int e = tid + i * 128;
            int r = e >> 3, g = e & 7;
            CP_ASYNC16(sAu[bf] + SWZ128(r * 128 + g * 16),
                       abase + (size_t)r * HD + g * 8);
            CP_ASYNC16(sBu[bf] + SWZ128(r * 128 + g * 16),
                       g_wp16 + (size_t)(e0 + r) * 384 + hc * 64 + g * 8);
        }
    };

    issue(0); CP_COMMIT();
    for (int hc = 0; hc < 6; hc++) {
        if (hc < 5) { issue(hc + 1); CP_COMMIT(); CP_WAIT1(); }
        else        { CP_WAIT0(); }
        __syncthreads();
        int bf = hc & 1;
        #pragma unroll
        for (int ks = 0; ks < 4; ks++) {
            int col16 = ks * 2 + (lane >> 4);
            uint32_t a0, a1, a2, a3;
            {
                int row = wid * 16 + (lane & 15);
                ldsm_x4(a0, a1, a2, a3, sAu[bf] + SWZ128(row * 128 + col16 * 16));
            }
            uint32_t bb[8][2];
            #pragma unroll
            for (int np = 0; np < 4; np++) {
                int n = np * 16 + (lane & 15);
                ldsm_x4(bb[np*2][0], bb[np*2+1][0], bb[np*2][1], bb[np*2+1][1],
                        sBu[bf] + SWZ128(n * 128 + col16 * 16));
            }
            #pragma unroll
            for (int nb = 0; nb < 8; nb++)
                mma16816(acc[nb], a0, a1, a2, a3, bb[nb][0], bb[nb][1]);
        }
        __syncthreads();
    }

    int mg = m0 + wid * 16 + (lane >> 2);
    float* orow = out + (size_t)mg * NC + e0;
    #pragma unroll
    for (int nb = 0; nb < 8; nb++) {
        int n = nb * 8 + (lane & 3) * 2;
        float2 bb2 = *(const float2*)(bp + e0 + n);
        *(float2*)(orow + n) =
            make_float2(acc[nb][0] + bb2.x, acc[nb][1] + bb2.y);
        *(float2*)(orow + 8*NC + n) =
            make_float2(acc[nb][2] + bb2.x, acc[nb][3] + bb2.y);
    }
}

// ---------------------------------------------------------------------------

extern "C" void kernel_launch(void* const* d_in, const int* in_sizes, int n_in,
                              void* d_out, int out_size)
{
    const float* x  = (const float*)d_in[0];
    const float* Wq = (const float*)d_in[1];
    const float* Wk = (const float*)d_in[2];
    const float* Wv = (const float*)d_in[3];
    const float* Wp = (const float*)d_in[4];
    const float* bp = (const float*)d_in[5];
    float* out = (float*)d_out;

    cudaFuncSetAttribute(qkv_attn_kernel,
                         cudaFuncAttributeMaxDynamicSharedMemorySize, FUSED_SMEM);

    convert_all_kernel<<<792, 256>>>(x, Wq, Wk, Wv, Wp);
    qkv_attn_kernel<<<dim3(NH, NB), 256, FUSED_SMEM>>>();
    proj_tc_kernel<<<dim3(NM/64, NC/64), 128>>>(bp, out);
}

// round 16
// speedup vs baseline: 1.4734x; 1.1304x over previous
#include <cuda_runtime.h>
#include <cuda_fp16.h>
#include <cstdint>

#define NC 384
#define NH 6
#define HD 64
#define NB 64
#define NT 256
#define NM (NB*NT)
#define SOFT_SCALE 0.125f

// fp16 scratch (allocation-free rule: __device__ globals)
__device__ __align__(128) __half g_x16[(size_t)NM*NC];
__device__ __align__(128) __half g_wqkv16[(size_t)NH*3*HD*NC];  // [h][mat][n=64][k=384]
__device__ __align__(128) __half g_wp16[(size_t)NC*NC];         // [n=384][k=384]
__device__ __align__(128) __half g_att16[(size_t)NB*NH*NT*HD];

#define SWZ128(b) ((b) ^ (((b) >> 3) & 0x70))

static __device__ __forceinline__ uint32_t smem_u32(const void* p) {
    uint32_t a;
    asm("{ .reg .u64 t; cvta.to.shared.u64 t, %1; cvt.u32.u64 %0, t; }"
        : "=r"(a) : "l"(p));
    return a;
}
static __device__ __forceinline__ void ldsm_x4(
    uint32_t& r0, uint32_t& r1, uint32_t& r2, uint32_t& r3, uint32_t addr)
{
    asm volatile("ldmatrix.sync.aligned.m8n8.x4.shared.b16 {%0,%1,%2,%3}, [%4];"
                 : "=r"(r0), "=r"(r1), "=r"(r2), "=r"(r3) : "r"(addr));
}
static __device__ __forceinline__ void ldsm_x4_t(
    uint32_t& r0, uint32_t& r1, uint32_t& r2, uint32_t& r3, uint32_t addr)
{
    asm volatile("ldmatrix.sync.aligned.m8n8.x4.trans.shared.b16 {%0,%1,%2,%3}, [%4];"
                 : "=r"(r0), "=r"(r1), "=r"(r2), "=r"(r3) : "r"(addr));
}
static __device__ __forceinline__ void mma16816(
    float* c, uint32_t a0, uint32_t a1, uint32_t a2, uint32_t a3,
    uint32_t b0, uint32_t b1)
{
    asm volatile(
        "mma.sync.aligned.m16n8k16.row.col.f32.f16.f16.f32 "
        "{%0,%1,%2,%3}, {%4,%5,%6,%7}, {%8,%9}, {%0,%1,%2,%3};"
        : "+f"(c[0]), "+f"(c[1]), "+f"(c[2]), "+f"(c[3])
        : "r"(a0), "r"(a1), "r"(a2), "r"(a3), "r"(b0), "r"(b1));
}
static __device__ __forceinline__ uint32_t f2h2(float a, float b) {
    __half2 h = __floats2half2_rn(a, b);
    return *reinterpret_cast<uint32_t*>(&h);
}
#define CP_ASYNC16(d, s) \
    asm volatile("cp.async.ca.shared.global [%0], [%1], 16;" :: "r"(d), "l"(s))
#define CP_COMMIT() asm volatile("cp.async.commit_group;" ::: "memory")
#define CP_WAIT0()  asm volatile("cp.async.wait_group 0;" ::: "memory")
#define CP_WAIT1()  asm volatile("cp.async.wait_group 1;" ::: "memory")

// ===========================================================================
// Prologue: converts, ZERO smem (full occupancy).
// blocks [0,768): x -> fp16, 32 floats/thread, 8 independent LDG.128 (MLP=8).
// blocks [768,1200): qkv weights -> fp16 [h][mat][n][k], register transpose.
// blocks [1200,1344): Wp -> fp16 [n][k], register transpose.
// ===========================================================================
__global__ __launch_bounds__(256) void convert_all_kernel(
    const float* __restrict__ x,
    const float* __restrict__ Wq, const float* __restrict__ Wk,
    const float* __restrict__ Wv, const float* __restrict__ Wp)
{
    int tid = threadIdx.x;

    if (blockIdx.x < 768) {
        size_t base = (size_t)blockIdx.x * 8192;   // 256 thr * 32 floats
        float4 u[8];
        #pragma unroll
        for (int i = 0; i < 8; i++)
            u[i] = *(const float4*)(x + base + (size_t)i * 1024 + tid * 4);
        #pragma unroll
        for (int i = 0; i < 8; i++) {
            uint2 pk = make_uint2(f2h2(u[i].x, u[i].y), f2h2(u[i].z, u[i].w));
            *(uint2*)(g_x16 + base + (size_t)i * 1024 + tid * 4) = pk;
        }
    } else if (blockIdx.x < 1200) {
        // qkv: item = (slot=h*3+mat, kg 0..95, n 0..63); 4 strided loads -> uint2
        int e = (blockIdx.x - 768) * 256 + tid;
        int slot = e / (64 * 96);
        int rem  = e % (64 * 96);
        int kg = rem >> 6, n = rem & 63;
        int h = slot / 3, mat = slot % 3;
        const float* Wsrcs[3] = {Wq, Wk, Wv};
        const float* W = Wsrcs[mat] + (size_t)h * NC * HD + (size_t)kg * 4 * HD + n;
        float w0 = W[0], w1 = W[HD], w2 = W[2*HD], w3 = W[3*HD];
        *(uint2*)(g_wqkv16 + (size_t)slot * 64 * 384 + n * 384 + kg * 4) =
            make_uint2(f2h2(w0, w1), f2h2(w2, w3));
    } else {
        // Wp: item = (kg 0..95, n 0..383)
        int e = (blockIdx.x - 1200) * 256 + tid;
        int kg = e / 384, n = e % 384;
        const float* W = Wp + (size_t)kg * 4 * NC + n;
        float w0 = W[0], w1 = W[NC], w2 = W[2*NC], w3 = W[3*NC];
        *(uint2*)(g_wp16 + (size_t)n * 384 + kg * 4) =
            make_uint2(f2h2(w0, w1), f2h2(w2, w3));
    }
}

// ===========================================================================
// Fused QKV-GEMM + causal flash attention. grid (NH, NB), block 256 (8 warps).
// Dynamic smem (176KB). (unchanged)
// ===========================================================================
#define QS_OFF   0
#define KS_OFF   32768
#define VS_OFF   65536
#define AST_OFF  98304
#define BST_OFF  131072
#define FUSED_SMEM (131072 + 2*24576)   // 180224

extern __shared__ unsigned char sm_fused[];

__global__ __launch_bounds__(256) void qkv_attn_kernel()
{
    int tid = threadIdx.x;
    int wid = tid >> 5, lane = tid & 31;
    int h = blockIdx.x;
    int b = blockIdx.y;

    const uint32_t sQ = smem_u32(sm_fused) + QS_OFF;
    const uint32_t sK = smem_u32(sm_fused) + KS_OFF;
    const uint32_t sV = smem_u32(sm_fused) + VS_OFF;
    const uint32_t sA[2] = {smem_u32(sm_fused) + AST_OFF,
                            smem_u32(sm_fused) + AST_OFF + 16384};
    const uint32_t sB[2] = {smem_u32(sm_fused) + BST_OFF,
                            smem_u32(sm_fused) + BST_OFF + 24576};

    const __half* xsrc = g_x16 + (size_t)b * NT * NC;
    const __half* wsrc = g_wqkv16 + (size_t)h * 192 * 384;

    // ---------------- Phase 1: Q|K|V GEMM ----------------
    for (int pass = 0; pass < 2; pass++) {
        float acc[24][4] = {};

        auto issue = [&](int c) {
            int c0 = c * 64, bf = c & 1;
            #pragma unroll
            for (int i = 0; i < 4; i++) {            // A: 1024 items
                int e = tid + i * 256;
                int r = e >> 3, g = e & 7;
                CP_ASYNC16(sA[bf] + SWZ128(r * 128 + g * 16),
                           xsrc + (size_t)(pass * 128 + r) * NC + c0 + g * 8);
            }
            #pragma unroll
            for (int i = 0; i < 6; i++) {            // B: 1536 items
                int e = tid + i * 256;
                int n = e >> 3, g = e & 7;
                CP_ASYNC16(sB[bf] + SWZ128(n * 128 + g * 16),
                           wsrc + (size_t)n * 384 + c0 + g * 8);
            }
        };

        issue(0); CP_COMMIT();
        for (int c = 0; c < 6; c++) {
            if (c < 5) { issue(c + 1); CP_COMMIT(); CP_WAIT1(); }
            else       { CP_WAIT0(); }
            __syncthreads();
            int bf = c & 1;
            #pragma unroll
            for (int ks = 0; ks < 4; ks++) {
                int col16 = ks * 2 + (lane >> 4);
                uint32_t a0, a1, a2, a3;
                {
                    int row = wid * 16 + (lane & 15);
                    ldsm_x4(a0, a1, a2, a3, sA[bf] + SWZ128(row * 128 + col16 * 16));
                }
                #pragma unroll
                for (int nb16 = 0; nb16 < 12; nb16++) {
                    int n = nb16 * 16 + (lane & 15);
                    uint32_t b0a, b0b, b1a, b1b;
                    ldsm_x4(b0a, b0b, b1a, b1b, sB[bf] + SWZ128(n * 128 + col16 * 16));
                    mma16816(acc[nb16*2],   a0, a1, a2, a3, b0a, b1a);
                    mma16816(acc[nb16*2+1], a0, a1, a2, a3, b0b, b1b);
                }
            }
            __syncthreads();
        }

        // epilogue: store 16 rows x 192 cols to Qs/Ks/Vs (Q scaled)
        unsigned char* smb = sm_fused;
        int r0 = wid * 16 + (lane >> 2);
        int t0 = pass * 128 + r0;
        #pragma unroll
        for (int nb = 0; nb < 24; nb++) {
            int mat = nb >> 3;
            int col = (nb & 7) * 8 + (lane & 3) * 2;
            float sc = (mat == 0) ? SOFT_SCALE : 1.0f;
            int base = (mat == 0 ? QS_OFF : (mat == 1 ? KS_OFF : VS_OFF));
            *(uint32_t*)(smb + base + SWZ128(t0 * 128 + col * 2)) =
                f2h2(acc[nb][0]*sc, acc[nb][1]*sc);
            *(uint32_t*)(smb + base + SWZ128((t0 + 8) * 128 + col * 2)) =
                f2h2(acc[nb][2]*sc, acc[nb][3]*sc);
        }
    }
    __syncthreads();   // all Q/K/V in smem

    // ---------------- Phase 2: causal attention ----------------
    __half* obase = g_att16 + ((size_t)(b * NH + h) * NT) * HD;

    #pragma unroll
    for (int p2 = 0; p2 < 2; p2++) {
        int R = p2 * 128 + wid * 16;

        uint32_t qf[4][4];
        #pragma unroll
        for (int ks = 0; ks < 4; ks++) {
            int col16 = ks * 2 + (lane >> 4);
            ldsm_x4(qf[ks][0], qf[ks][1], qf[ks][2], qf[ks][3],
                    sQ + SWZ128((R + (lane & 15)) * 128 + col16 * 16));
        }

        float o[8][4] = {};
        float mrow[2] = {-1e30f, -1e30f};
        float lrow[2] = {};
        int lt = (R + 15) >> 6;

        for (int st = 0; st <= lt; st++) {
            // S = Q K^T
            float sacc[8][4] = {};
            #pragma unroll
            for (int ks = 0; ks < 4; ks++) {
                int col16 = ks * 2 + (lane >> 4);
                #pragma unroll
                for (int np = 0; np < 4; np++) {
                    int n = st * 64 + np * 16 + (lane & 15);
                    uint32_t b0a, b0b, b1a, b1b;
                    ldsm_x4(b0a, b0b, b1a, b1b, sK + SWZ128(n * 128 + col16 * 16));
                    mma16816(sacc[np*2],   qf[ks][0], qf[ks][1], qf[ks][2], qf[ks][3], b0a, b1a);
                    mma16816(sacc[np*2+1], qf[ks][0], qf[ks][1], qf[ks][2], qf[ks][3], b0b, b1b);
                }
            }

            if (st == lt) {
                int r0 = R + (lane >> 2);
                #pragma unroll
                for (int nb = 0; nb < 8; nb++) {
                    int cg = st*64 + nb*8 + (lane & 3) * 2;
                    if (cg     > r0    ) sacc[nb][0] = -1e30f;
                    if (cg + 1 > r0    ) sacc[nb][1] = -1e30f;
                    if (cg     > r0 + 8) sacc[nb][2] = -1e30f;
                    if (cg + 1 > r0 + 8) sacc[nb][3] = -1e30f;
                }
            }

            #pragma unroll
            for (int hf = 0; hf < 2; hf++) {
                float mx = -1e30f;
                #pragma unroll
                for (int nb = 0; nb < 8; nb++)
                    mx = fmaxf(mx, fmaxf(sacc[nb][hf*2], sacc[nb][hf*2+1]));
                mx = fmaxf(mx, __shfl_xor_sync(0xffffffffu, mx, 1));
                mx = fmaxf(mx, __shfl_xor_sync(0xffffffffu, mx, 2));
                float mnew = fmaxf(mrow[hf], mx);
                float corr = __expf(mrow[hf] - mnew);
                float rs = 0.f;
                #pragma unroll
                for (int nb = 0; nb < 8; nb++) {
                    float p0 = __expf(sacc[nb][hf*2]   - mnew);
                    float p1 = __expf(sacc[nb][hf*2+1] - mnew);
                    sacc[nb][hf*2] = p0; sacc[nb][hf*2+1] = p1;
                    rs += p0 + p1;
                }
                rs += __shfl_xor_sync(0xffffffffu, rs, 1);
                rs += __shfl_xor_sync(0xffffffffu, rs, 2);
                lrow[hf] = lrow[hf] * corr + rs;
                mrow[hf] = mnew;
                #pragma unroll
                for (int nb = 0; nb < 8; nb++) {
                    o[nb][hf*2]   *= corr;
                    o[nb][hf*2+1] *= corr;
                }
            }

            // O += P V
            #pragma unroll
            for (int ks = 0; ks < 4; ks++) {
                uint32_t pa0 = f2h2(sacc[ks*2  ][0], sacc[ks*2  ][1]);
                uint32_t pa1 = f2h2(sacc[ks*2  ][2], sacc[ks*2  ][3]);
                uint32_t pa2 = f2h2(sacc[ks*2+1][0], sacc[ks*2+1][1]);
                uint32_t pa3 = f2h2(sacc[ks*2+1][2], sacc[ks*2+1][3]);
                #pragma unroll
                for (int np = 0; np < 4; np++) {
                    int m = lane >> 3;
                    int row = st * 64 + ks * 16 + ((m & 1) << 3) + (lane & 7);
                    int colb = (np * 16 + ((m & 2) << 2)) * 2;
                    uint32_t v0, v1, v2, v3;
                    ldsm_x4_t(v0, v1, v2, v3, sV + SWZ128(row * 128 + colb));
                    mma16816(o[np*2],   pa0, pa1, pa2, pa3, v0, v1);
                    mma16816(o[np*2+1], pa0, pa1, pa2, pa3, v2, v3);
                }
            }
        }

        float inv0 = 1.0f / lrow[0], inv1 = 1.0f / lrow[1];
        int t0 = R + (lane >> 2);
        __half* ob = obase + (size_t)t0 * HD;
        #pragma unroll
        for (int nb = 0; nb < 8; nb++) {
            int n = nb*8 + (lane & 3) * 2;
            *(uint32_t*)(ob + n)        = f2h2(o[nb][0]*inv0, o[nb][1]*inv0);
            *(uint32_t*)(ob + 8*HD + n) = f2h2(o[nb][2]*inv1, o[nb][3]*inv1);
        }
    }
}

// ===========================================================================
// Kernel 3: output projection + bias. grid (256, 6), block 128 (4 warps).
// (unchanged)
// ===========================================================================
__global__ __launch_bounds__(128) void proj_tc_kernel(
    const float* __restrict__ bp, float* __restrict__ out)
{
    __shared__ __align__(1024) __half smA[2][64*64];
    __shared__ __align__(1024) __half smB[2][64*64];

    int tid = threadIdx.x;
    int wid = tid >> 5, lane = tid & 31;
    int m0 = blockIdx.x * 64;
    int e0 = blockIdx.y * 64;
    int b  = m0 >> 8;
    int t0 = m0 & 255;

    const uint32_t sAu[2] = {smem_u32(smA[0]), smem_u32(smA[1])};
    const uint32_t sBu[2] = {smem_u32(smB[0]), smem_u32(smB[1])};

    float acc[8][4] = {};

    auto issue = [&](int hc) {
        int bf = hc & 1;
        const __half* abase = g_att16 + ((size_t)(b * NH + hc) * NT + t0) * HD;
        #pragma unroll
        for (int i = 0; i < 4; i++) {
            int e = tid + i * 128;
            int r = e >> 3, g = e & 7;
            CP_ASYNC16(sAu[bf] + SWZ128(r * 128 + g * 16),
                       abase + (size_t)r * HD + g * 8);
            CP_ASYNC16(sBu[bf] + SWZ128(r * 128 + g * 16),
                       g_wp16 + (size_t)(e0 + r) * 384 + hc * 64 + g * 8);
        }
    };

    issue(0); CP_COMMIT();
    for (int hc = 0; hc < 6; hc++) {
        if (hc < 5) { issue(hc + 1); CP_COMMIT(); CP_WAIT1(); }
        else        { CP_WAIT0(); }
        __syncthreads();
        int bf = hc & 1;
        #pragma unroll
        for (int ks = 0; ks < 4; ks++) {
            int col16 = ks * 2 + (lane >> 4);
            uint32_t a0, a1, a2, a3;
            {
                int row = wid * 16 + (lane & 15);
                ldsm_x4(a0, a1, a2, a3, sAu[bf] + SWZ128(row * 128 + col16 * 16));
            }
            uint32_t bb[8][2];
            #pragma unroll
            for (int np = 0; np < 4; np++) {
                int n = np * 16 + (lane & 15);
                ldsm_x4(bb[np*2][0], bb[np*2+1][0], bb[np*2][1], bb[np*2+1][1],
                        sBu[bf] + SWZ128(n * 128 + col16 * 16));
            }
            #pragma unroll
            for (int nb = 0; nb < 8; nb++)
                mma16816(acc[nb], a0, a1, a2, a3, bb[nb][0], bb[nb][1]);
        }
        __syncthreads();
    }

    int mg = m0 + wid * 16 + (lane >> 2);
    float* orow = out + (size_t)mg * NC + e0;
    #pragma unroll
    for (int nb = 0; nb < 8; nb++) {
        int n = nb * 8 + (lane & 3) * 2;
        float2 bb2 = *(const float2*)(bp + e0 + n);
        *(float2*)(orow + n) =
            make_float2(acc[nb][0] + bb2.x, acc[nb][1] + bb2.y);
        *(float2*)(orow + 8*NC + n) =
            make_float2(acc[nb][2] + bb2.x, acc[nb][3] + bb2.y);
    }
}

// ---------------------------------------------------------------------------

extern "C" void kernel_launch(void* const* d_in, const int* in_sizes, int n_in,
                              void* d_out, int out_size)
{
    const float* x  = (const float*)d_in[0];
    const float* Wq = (const float*)d_in[1];
    const float* Wk = (const float*)d_in[2];
    const float* Wv = (const float*)d_in[3];
    const float* Wp = (const float*)d_in[4];
    const float* bp = (const float*)d_in[5];
    float* out = (float*)d_out;

    cudaFuncSetAttribute(qkv_attn_kernel,
                         cudaFuncAttributeMaxDynamicSharedMemorySize, FUSED_SMEM);

    convert_all_kernel<<<1344, 256>>>(x, Wq, Wk, Wv, Wp);
    qkv_attn_kernel<<<dim3(NH, NB), 256, FUSED_SMEM>>>();
    proj_tc_kernel<<<dim3(NM/64, NC/64), 128>>>(bp, out);
}